// round 3
// baseline (speedup 1.0000x reference)
#include <cuda_runtime.h>
#include <math.h>

#define BB 4
#define CCH 64

__device__ __align__(16) float g_t0  [(size_t)4*64*128*128*4];
__device__ __align__(16) float g_tpw0[(size_t)4*64*128*128*4];
__device__ __align__(16) float g_t1  [(size_t)4*64*64*64*4];
__device__ __align__(16) float g_tpw1[(size_t)4*64*64*64*4];
__device__ float g_ll1 [(size_t)4*64*128*128];
__device__ float g_nxt1[(size_t)4*64*128*128];
__device__ float g_off0[(size_t)4*2*128*128];
__device__ float g_off1[(size_t)4*2*64*64];
__device__ float g_offacc[(size_t)4*4*2*128*128];

// Haar analysis: plain src -> interleaved dst (b,c,h2,w2,4); optional LL copy
__global__ void k_wt(const float* __restrict__ src, float4* __restrict__ dst,
                     float* __restrict__ llout, int Hs, int Ws,
                     size_t chStep, size_t bStride) {
    int h2 = Hs >> 1, w2 = Ws >> 1;
    int idx = blockIdx.x * blockDim.x + threadIdx.x;
    int total = BB * CCH * h2 * w2;
    if (idx >= total) return;
    int q = idx % w2; int t = idx / w2;
    int p = t % h2;  t /= h2;
    int g = t % CCH; int b = t / CCH;
    const float* s = src + (size_t)b*bStride + (size_t)g*chStep + (size_t)(2*p)*Ws + 2*q;
    float x00=s[0], x01=s[1], x10=s[Ws], x11=s[Ws+1];
    float LL=0.5f*(x00+x01+x10+x11), A=0.5f*(x00+x01-x10-x11);
    float Bv=0.5f*(x00-x01+x10-x11), Cv=0.5f*(x00-x01-x10+x11);
    size_t o = ((size_t)(b*CCH+g)*h2 + p)*w2 + q;
    dst[o] = make_float4(LL,A,Bv,Cv);
    if (llout) llout[o] = LL;
}

// dense 3x3 conv 256->2, 4-way channel-split partials. grid(W/32,H/32,B*4) block(32,8)
__global__ void k_off2(const float4* __restrict__ t4, const float* __restrict__ ow,
                       float* __restrict__ acc, int Hh, int Ww) {
    __shared__ float wsm[1152];
    __shared__ float tile[8][34][34];
    int tx=threadIdx.x, ty=threadIdx.y, tid=ty*32+tx;
    int split = blockIdx.z & 3, b = blockIdx.z >> 2;
    int cb = split*64, gb = split*16;
    for (int i=tid;i<1152;i+=256){int o=i/576,rem=i%576;wsm[i]=ow[(o*256+cb+rem/9)*9+rem%9];}
    size_t plane = (size_t)Hh*Ww;
    const float4* tb = t4 + (size_t)b*64*plane;
    int gx0 = blockIdx.x*32-1, gy0 = blockIdx.y*32-1;
    float a0[4]={0,0,0,0}, a1[4]={0,0,0,0};
    for (int gg=0; gg<16; gg+=2) {
        __syncthreads();
        for (int i=tid;i<2*1156;i+=256){
            int g2=i/1156,pos=i%1156,yy=pos/34,xx=pos%34;
            int gy=gy0+yy, gx=gx0+xx;
            float4 v = make_float4(0.f,0.f,0.f,0.f);
            if (gy>=0&&gy<Hh&&gx>=0&&gx<Ww) v = tb[(size_t)(gb+gg+g2)*plane+(size_t)gy*Ww+gx];
            tile[g2*4+0][yy][xx]=v.x; tile[g2*4+1][yy][xx]=v.y;
            tile[g2*4+2][yy][xx]=v.z; tile[g2*4+3][yy][xx]=v.w;
        }
        __syncthreads();
        #pragma unroll
        for (int c8=0;c8<8;c8++){
            int lc = gg*4 + c8;
            float w0[9], w1[9];
            #pragma unroll
            for (int k=0;k<9;k++){w0[k]=wsm[lc*9+k];w1[k]=wsm[576+lc*9+k];}
            float vals[6][3];
            #pragma unroll
            for (int rr=0;rr<6;rr++)
                #pragma unroll
                for (int kx=0;kx<3;kx++) vals[rr][kx]=tile[c8][4*ty+rr][tx+kx];
            #pragma unroll
            for (int r=0;r<4;r++)
                #pragma unroll
                for (int ky=0;ky<3;ky++)
                    #pragma unroll
                    for (int kx=0;kx<3;kx++){
                        float v=vals[r+ky][kx];
                        a0[r]+=v*w0[ky*3+kx]; a1[r]+=v*w1[ky*3+kx];
                    }
        }
    }
    float* ob = acc + (((size_t)split*4 + b)*2)*plane;
    int px = blockIdx.x*32+tx;
    #pragma unroll
    for (int r=0;r<4;r++){
        int py = blockIdx.y*32 + ty*4 + r;
        ob[(size_t)py*Ww+px]=a0[r];
        ob[plane+(size_t)py*Ww+px]=a1[r];
    }
}

__device__ __forceinline__ float reflect_clip(float v, float size) {
    float two = 2.f*size;
    float r = fmodf(v+0.5f, two);
    if (r < 0.f) r += two;
    if (r > size) r = two - r;
    r -= 0.5f;
    return fminf(fmaxf(r, 0.f), size-1.f);
}

// sum partials + bias -> tanh -> reflect-clipped sample coords
__global__ void k_offfin(const float* __restrict__ acc, const float* __restrict__ ob,
                         float* __restrict__ offmap, int Hh, int Ww) {
    int idx = blockIdx.x*blockDim.x + threadIdx.x;
    int n = BB*Hh*Ww;
    if (idx >= n) return;
    int px = idx % Ww; int t = idx / Ww;
    int py = t % Hh; int b = t / Hh;
    size_t plane = (size_t)Hh*Ww, pix = (size_t)py*Ww+px;
    float s0=0.f, s1=0.f;
    #pragma unroll
    for (int s=0;s<4;s++){
        const float* base = acc + (((size_t)s*4+b)*2)*plane + pix;
        s0 += base[0]; s1 += base[plane];
    }
    float offx = tanhf(s0 + ob[0]);
    float offy = tanhf(s1 + ob[1]);
    float w = (float)Ww, h = (float)Hh;
    float ix = ((float)px + offx) * (w/(w-1.f)) - 0.5f;
    float iy = ((float)py + offy) * (h/(h-1.f)) - 0.5f;
    offmap[(size_t)b*2*plane + pix]   = reflect_clip(ix, w);
    offmap[((size_t)b*2+1)*plane+pix] = reflect_clip(iy, h);
}

// fused grid_sample + depthwise3x3 + relu + grouped1x1 + wscale. grid(W/16,H/16,B) block(16,16)
__global__ void k_sdp(const float4* __restrict__ t4, const float* __restrict__ offmap,
                      const float* __restrict__ dww, const float* __restrict__ pww,
                      const float* __restrict__ wsc, float4* __restrict__ outp,
                      int Hh, int Ww) {
    __shared__ __align__(16) float sdw[256*12];
    __shared__ float4 spw[256];
    __shared__ float4 sws[64];
    __shared__ float sx[324], sy[324];
    __shared__ float4 td[324];
    int tx=threadIdx.x, ty=threadIdx.y, tid=ty*16+tx;
    int b = blockIdx.z;
    for (int i=tid;i<256*9;i+=256){int c=i/9,k=i%9;sdw[c*12+k]=dww[i];}
    if (tid<256) spw[tid]=make_float4(pww[tid*4],pww[tid*4+1],pww[tid*4+2],pww[tid*4+3]);
    if (tid<64)  sws[tid]=make_float4(wsc[tid*4],wsc[tid*4+1],wsc[tid*4+2],wsc[tid*4+3]);
    size_t plane = (size_t)Hh*Ww;
    const float* ofx = offmap + (size_t)b*2*plane;
    const float* ofy = ofx + plane;
    int gx0 = blockIdx.x*16-1, gy0 = blockIdx.y*16-1;
    for (int i=tid;i<324;i+=256){
        int xx=i%18, yy=i/18;
        int gx=gx0+xx, gy=gy0+yy;
        float vx=-1.f, vy=-1.f;
        if (gx>=0&&gx<Ww&&gy>=0&&gy<Hh){size_t p=(size_t)gy*Ww+gx; vx=ofx[p]; vy=ofy[p];}
        sx[i]=vx; sy[i]=vy;
    }
    const float4* tb = t4 + (size_t)b*64*plane;
    int px = blockIdx.x*16+tx, py = blockIdx.y*16+ty;
    for (int g=0; g<64; g++) {
        __syncthreads();
        const float4* tg = tb + (size_t)g*plane;
        for (int i=tid;i<324;i+=256){
            float ix = sx[i];
            float4 r = make_float4(0.f,0.f,0.f,0.f);
            if (ix >= 0.f) {
                float iy = sy[i];
                float x0 = floorf(ix), y0 = floorf(iy);
                float wx = ix-x0, wy = iy-y0;
                int x0i=(int)x0, y0i=(int)y0;
                int x1i=min(x0i+1,Ww-1), y1i=min(y0i+1,Hh-1);
                float4 v00=tg[(size_t)y0i*Ww+x0i], v01=tg[(size_t)y0i*Ww+x1i];
                float4 v10=tg[(size_t)y1i*Ww+x0i], v11=tg[(size_t)y1i*Ww+x1i];
                float w00=(1.f-wy)*(1.f-wx), w01=(1.f-wy)*wx;
                float w10=wy*(1.f-wx), w11=wy*wx;
                r.x=v00.x*w00+v01.x*w01+v10.x*w10+v11.x*w11;
                r.y=v00.y*w00+v01.y*w01+v10.y*w10+v11.y*w11;
                r.z=v00.z*w00+v01.z*w01+v10.z*w10+v11.z*w11;
                r.w=v00.w*w00+v01.w*w01+v10.w*w10+v11.w*w11;
            }
            td[i]=r;
        }
        __syncthreads();
        float wd[4][9];
        #pragma unroll
        for (int c=0;c<4;c++)
            #pragma unroll
            for (int k=0;k<9;k++) wd[c][k]=sdw[(g*4+c)*12+k];
        float a0=0.f,a1=0.f,a2=0.f,a3=0.f;
        #pragma unroll
        for (int ky=0;ky<3;ky++)
            #pragma unroll
            for (int kx=0;kx<3;kx++){
                float4 v = td[(ty+ky)*18+tx+kx];
                int k = ky*3+kx;
                a0+=v.x*wd[0][k]; a1+=v.y*wd[1][k];
                a2+=v.z*wd[2][k]; a3+=v.w*wd[3][k];
            }
        float r0=fmaxf(a0,0.f), r1=fmaxf(a1,0.f), r2=fmaxf(a2,0.f), r3=fmaxf(a3,0.f);
        float4 p0=spw[g*4],p1=spw[g*4+1],p2=spw[g*4+2],p3=spw[g*4+3],wsv=sws[g];
        float4 o;
        o.x=(r0*p0.x+r1*p0.y+r2*p0.z+r3*p0.w)*wsv.x;
        o.y=(r0*p1.x+r1*p1.y+r2*p1.z+r3*p1.w)*wsv.y;
        o.z=(r0*p2.x+r1*p2.y+r2*p2.z+r3*p2.w)*wsv.z;
        o.w=(r0*p3.x+r1*p3.y+r2*p3.z+r3*p3.w)*wsv.w;
        outp[((size_t)b*64+g)*plane + (size_t)py*Ww + px] = o;
    }
}

// inverse Haar: interleaved coeff (h2,w2) -> plain (2h2,2w2)
__global__ void k_iwt(const float4* __restrict__ coef, float* __restrict__ outp,
                      int h2, int w2) {
    int idx = blockIdx.x*blockDim.x + threadIdx.x;
    int total = BB*CCH*h2*w2;
    if (idx >= total) return;
    int j = idx % w2; int t = idx / w2;
    int i = t % h2;  t /= h2;
    int c = t % CCH; int b = t / CCH;
    float4 v = coef[((size_t)(b*CCH+c)*h2 + i)*w2 + j];
    float LL=v.x, A=v.y, Bv=v.z, Cv=v.w;
    int Wo = 2*w2;
    float* o = outp + ((size_t)(b*CCH+c)*(2*h2) + 2*i)*Wo + 2*j;
    o[0]    = 0.5f*(LL+A+Bv+Cv);
    o[1]    = 0.5f*(LL+A-Bv-Cv);
    o[Wo]   = 0.5f*(LL-A+Bv-Cv);
    o[Wo+1] = 0.5f*(LL-A-Bv+Cv);
}

// final: level0 iwt + base depthwise conv + bias*scale + gamma add
__global__ void k_final(const float* __restrict__ x, const float4* __restrict__ coef,
                        const float* __restrict__ nxt, const float* __restrict__ bw,
                        const float* __restrict__ bb_, const float* __restrict__ bscale,
                        const float* __restrict__ gammap, float* __restrict__ outp) {
    int idx = blockIdx.x*blockDim.x + threadIdx.x;
    int total = BB*CCH*128*128;
    if (idx >= total) return;
    int j = idx % 128; int t = idx / 128;
    int i = t % 128; t /= 128;
    int c = t % CCH; int b = t / CCH;
    size_t ci = ((size_t)(b*CCH+c)*128 + i)*128 + j;
    float4 v = coef[ci];
    float LL = v.x + nxt[ci];
    float A=v.y, Bv=v.z, Cv=v.w;
    float rec[2][2];
    rec[0][0]=0.5f*(LL+A+Bv+Cv); rec[0][1]=0.5f*(LL+A-Bv-Cv);
    rec[1][0]=0.5f*(LL-A+Bv-Cv); rec[1][1]=0.5f*(LL-A-Bv+Cv);
    float gm = gammap[0];
    const float* xp = x + (size_t)(b*CCH+c)*256*256;
    float wreg[9];
    #pragma unroll
    for (int k=0;k<9;k++) wreg[k]=__ldg(&bw[c*9+k]);
    float bias=__ldg(&bb_[c]), sc=__ldg(&bscale[c]);
    float xv[4][4];
    #pragma unroll
    for (int dy=0;dy<4;dy++){
        int yy = 2*i-1+dy;
        #pragma unroll
        for (int dx=0;dx<4;dx++){
            int xx = 2*j-1+dx;
            xv[dy][dx] = (yy>=0&&yy<256&&xx>=0&&xx<256) ? xp[(size_t)yy*256+xx] : 0.f;
        }
    }
    float* op = outp + (size_t)(b*CCH+c)*256*256;
    #pragma unroll
    for (int ri=0;ri<2;ri++)
        #pragma unroll
        for (int rj=0;rj<2;rj++){
            float a = 0.f;
            #pragma unroll
            for (int ky=0;ky<3;ky++)
                #pragma unroll
                for (int kx=0;kx<3;kx++)
                    a += xv[ri+ky][rj+kx]*wreg[ky*3+kx];
            op[(size_t)(2*i+ri)*256 + 2*j+rj] = (a+bias)*sc + gm*rec[ri][rj];
        }
}

extern "C" void kernel_launch(void* const* d_in, const int* in_sizes, int n_in,
                              void* d_out, int out_size) {
    const float* x       = (const float*)d_in[0];
    const float* base_w  = (const float*)d_in[1];
    const float* base_b  = (const float*)d_in[2];
    const float* base_sc = (const float*)d_in[3];
    const float* off_w   = (const float*)d_in[4];
    const float* off_b   = (const float*)d_in[5];
    const float* dw_w    = (const float*)d_in[6];
    const float* pw_w    = (const float*)d_in[7];
    const float* wscale  = (const float*)d_in[8];
    const float* gamma   = (const float*)d_in[9];
    float* out = (float*)d_out;

    float4 *t0, *tpw0, *t1, *tpw1;
    float *ll1, *nxt1, *off0, *off1, *offacc;
    cudaGetSymbolAddress((void**)&t0,   g_t0);
    cudaGetSymbolAddress((void**)&tpw0, g_tpw0);
    cudaGetSymbolAddress((void**)&t1,   g_t1);
    cudaGetSymbolAddress((void**)&tpw1, g_tpw1);
    cudaGetSymbolAddress((void**)&ll1,  g_ll1);
    cudaGetSymbolAddress((void**)&nxt1, g_nxt1);
    cudaGetSymbolAddress((void**)&off0, g_off0);
    cudaGetSymbolAddress((void**)&off1, g_off1);
    cudaGetSymbolAddress((void**)&offacc, g_offacc);

    // level 0 analysis: x(256^2) -> t0(128^2 interleaved) + ll1
    k_wt<<<16384, 256>>>(x, t0, ll1, 256, 256, (size_t)256*256, (size_t)64*256*256);
    // level 0 offsets
    k_off2<<<dim3(4,4,16), dim3(32,8)>>>(t0, off_w, offacc, 128, 128);
    k_offfin<<<256, 256>>>(offacc, off_b, off0, 128, 128);
    // level 0 snake+pw
    k_sdp<<<dim3(8,8,4), dim3(16,16)>>>(t0, off0, dw_w, pw_w, wscale, tpw0, 128, 128);
    // level 1 analysis: ll1(128^2) -> t1(64^2 interleaved)
    k_wt<<<4096, 256>>>(ll1, (float4*)t1, nullptr, 128, 128, (size_t)128*128, (size_t)64*128*128);
    // level 1 offsets
    k_off2<<<dim3(2,2,16), dim3(32,8)>>>(t1, off_w + 2*256*9, offacc, 64, 64);
    k_offfin<<<64, 256>>>(offacc, off_b + 2, off1, 64, 64);
    // level 1 snake+pw
    k_sdp<<<dim3(4,4,4), dim3(16,16)>>>(t1, off1, dw_w + 256*9, pw_w + 256*4,
                                        wscale + 256, tpw1, 64, 64);
    // level 1 inverse
    k_iwt<<<4096, 256>>>(tpw1, nxt1, 64, 64);
    // final fused
    k_final<<<16384, 256>>>(x, tpw0, nxt1, base_w, base_b, base_sc, gamma, out);
}

// round 4
// speedup vs baseline: 1.4970x; 1.4970x over previous
#include <cuda_runtime.h>
#include <math.h>

#define BB 4
#define CCH 64
#define G_PER 8

__device__ __align__(16) float g_t0  [(size_t)4*64*128*128*4];
__device__ __align__(16) float g_tpw0[(size_t)4*64*128*128*4];
__device__ __align__(16) float g_t1  [(size_t)4*64*64*64*4];
__device__ __align__(16) float g_tpw1[(size_t)4*64*64*64*4];
__device__ float g_ll1 [(size_t)4*64*128*128];
__device__ float g_nxt1[(size_t)4*64*128*128];
__device__ float g_off0[(size_t)4*2*128*128];
__device__ float g_off1[(size_t)4*2*64*64];
__device__ float g_offacc[(size_t)8*4*2*128*128];

// Haar analysis: plain src -> interleaved dst (b,c,h2,w2,4); optional LL copy
__global__ void k_wt(const float* __restrict__ src, float4* __restrict__ dst,
                     float* __restrict__ llout, int Hs, int Ws,
                     size_t chStep, size_t bStride) {
    int h2 = Hs >> 1, w2 = Ws >> 1;
    int idx = blockIdx.x * blockDim.x + threadIdx.x;
    int total = BB * CCH * h2 * w2;
    if (idx >= total) return;
    int q = idx % w2; int t = idx / w2;
    int p = t % h2;  t /= h2;
    int g = t % CCH; int b = t / CCH;
    const float* s = src + (size_t)b*bStride + (size_t)g*chStep + (size_t)(2*p)*Ws + 2*q;
    float x00=s[0], x01=s[1], x10=s[Ws], x11=s[Ws+1];
    float LL=0.5f*(x00+x01+x10+x11), A=0.5f*(x00+x01-x10-x11);
    float Bv=0.5f*(x00-x01+x10-x11), Cv=0.5f*(x00-x01-x10+x11);
    size_t o = ((size_t)(b*CCH+g)*h2 + p)*w2 + q;
    dst[o] = make_float4(LL,A,Bv,Cv);
    if (llout) llout[o] = LL;
}

// dense 3x3 conv 256->2, 8-way channel-split partials. grid(W/32,H/32,B*8) block(32,8)
__global__ void k_off2(const float4* __restrict__ t4, const float* __restrict__ ow,
                       float* __restrict__ acc, int Hh, int Ww) {
    __shared__ float wsm[576];            // 2 outputs x 32 ch x 9
    __shared__ float tile[8][34][34];
    int tx=threadIdx.x, ty=threadIdx.y, tid=ty*32+tx;
    int split = blockIdx.z & 7, b = blockIdx.z >> 3;
    int cb = split*32, gb = split*8;
    for (int i=tid;i<576;i+=256){int o=i/288,rem=i%288;wsm[i]=ow[(o*256+cb+rem/9)*9+rem%9];}
    size_t plane = (size_t)Hh*Ww;
    const float4* tb = t4 + (size_t)b*64*plane;
    int gx0 = blockIdx.x*32-1, gy0 = blockIdx.y*32-1;
    float a0[4]={0,0,0,0}, a1[4]={0,0,0,0};
    for (int gg=0; gg<8; gg+=2) {
        __syncthreads();
        for (int i=tid;i<2*1156;i+=256){
            int g2=i/1156,pos=i%1156,yy=pos/34,xx=pos%34;
            int gy=gy0+yy, gx=gx0+xx;
            float4 v = make_float4(0.f,0.f,0.f,0.f);
            if (gy>=0&&gy<Hh&&gx>=0&&gx<Ww) v = tb[(size_t)(gb+gg+g2)*plane+(size_t)gy*Ww+gx];
            tile[g2*4+0][yy][xx]=v.x; tile[g2*4+1][yy][xx]=v.y;
            tile[g2*4+2][yy][xx]=v.z; tile[g2*4+3][yy][xx]=v.w;
        }
        __syncthreads();
        #pragma unroll
        for (int c8=0;c8<8;c8++){
            int lc = gg*4 + c8;
            float w0[9], w1[9];
            #pragma unroll
            for (int k=0;k<9;k++){w0[k]=wsm[lc*9+k];w1[k]=wsm[288+lc*9+k];}
            float vals[6][3];
            #pragma unroll
            for (int rr=0;rr<6;rr++)
                #pragma unroll
                for (int kx=0;kx<3;kx++) vals[rr][kx]=tile[c8][4*ty+rr][tx+kx];
            #pragma unroll
            for (int r=0;r<4;r++)
                #pragma unroll
                for (int ky=0;ky<3;ky++)
                    #pragma unroll
                    for (int kx=0;kx<3;kx++){
                        float v=vals[r+ky][kx];
                        a0[r]+=v*w0[ky*3+kx]; a1[r]+=v*w1[ky*3+kx];
                    }
        }
    }
    float* ob = acc + (((size_t)split*4 + b)*2)*plane;
    int px = blockIdx.x*32+tx;
    #pragma unroll
    for (int r=0;r<4;r++){
        int py = blockIdx.y*32 + ty*4 + r;
        ob[(size_t)py*Ww+px]=a0[r];
        ob[plane+(size_t)py*Ww+px]=a1[r];
    }
}

__device__ __forceinline__ float reflect_clip(float v, float size) {
    float two = 2.f*size;
    float r = fmodf(v+0.5f, two);
    if (r < 0.f) r += two;
    if (r > size) r = two - r;
    r -= 0.5f;
    return fminf(fmaxf(r, 0.f), size-1.f);
}

// sum 8 partials + bias -> tanh -> reflect-clipped sample coords
__global__ void k_offfin(const float* __restrict__ acc, const float* __restrict__ ob,
                         float* __restrict__ offmap, int Hh, int Ww) {
    int idx = blockIdx.x*blockDim.x + threadIdx.x;
    int n = BB*Hh*Ww;
    if (idx >= n) return;
    int px = idx % Ww; int t = idx / Ww;
    int py = t % Hh; int b = t / Hh;
    size_t plane = (size_t)Hh*Ww, pix = (size_t)py*Ww+px;
    float s0=0.f, s1=0.f;
    #pragma unroll
    for (int s=0;s<8;s++){
        const float* base = acc + (((size_t)s*4+b)*2)*plane + pix;
        s0 += base[0]; s1 += base[plane];
    }
    float offx = tanhf(s0 + ob[0]);
    float offy = tanhf(s1 + ob[1]);
    float w = (float)Ww, h = (float)Hh;
    float ix = ((float)px + offx) * (w/(w-1.f)) - 0.5f;
    float iy = ((float)py + offy) * (h/(h-1.f)) - 0.5f;
    offmap[(size_t)b*2*plane + pix]   = reflect_clip(ix, w);
    offmap[((size_t)b*2+1)*plane+pix] = reflect_clip(iy, h);
}

// fused grid_sample + depthwise3x3 + relu + grouped1x1 + wscale.
// grid(W/16,H/16,B*8) block(16,16); each block: 8 groups, precomputed gather idx/weights
__global__ void k_sdp(const float4* __restrict__ t4, const float* __restrict__ offmap,
                      const float* __restrict__ dww, const float* __restrict__ pww,
                      const float* __restrict__ wsc, float4* __restrict__ outp,
                      int Hh, int Ww) {
    __shared__ __align__(16) int4  so4[324];
    __shared__ float4 swt[324];
    __shared__ float4 td[324];
    __shared__ float  sdw[G_PER*4*9];
    __shared__ float4 spw[G_PER*4];
    __shared__ float4 sws[G_PER];
    int tx=threadIdx.x, ty=threadIdx.y, tid=ty*16+tx;
    int b = blockIdx.z >> 3, g0 = (blockIdx.z & 7)*G_PER;
    for (int i=tid;i<G_PER*36;i+=256) sdw[i] = dww[g0*36 + i];
    if (tid < G_PER*4) spw[tid] = *(const float4*)&pww[(g0*4+tid)*4];
    if (tid < G_PER)   sws[tid] = *(const float4*)&wsc[(g0+tid)*4];
    size_t plane = (size_t)Hh*Ww;
    const float* ofx = offmap + (size_t)b*2*plane;
    const float* ofy = ofx + plane;
    int gx0 = blockIdx.x*16-1, gy0 = blockIdx.y*16-1;
    for (int i=tid;i<324;i+=256){
        int xx=i%18, yy=i/18;
        int gx=gx0+xx, gy=gy0+yy;
        int4 oo = make_int4(-1,0,0,0);
        float4 wv = make_float4(0.f,0.f,0.f,0.f);
        if (gx>=0&&gx<Ww&&gy>=0&&gy<Hh){
            size_t p=(size_t)gy*Ww+gx;
            float ix=ofx[p], iy=ofy[p];
            float x0=floorf(ix), y0=floorf(iy);
            float wx=ix-x0, wy=iy-y0;
            int x0i=(int)x0, y0i=(int)y0;
            int x1i=min(x0i+1,Ww-1), y1i=min(y0i+1,Hh-1);
            oo = make_int4(y0i*Ww+x0i, y0i*Ww+x1i, y1i*Ww+x0i, y1i*Ww+x1i);
            wv = make_float4((1.f-wy)*(1.f-wx),(1.f-wy)*wx,wy*(1.f-wx),wy*wx);
        }
        so4[i]=oo; swt[i]=wv;
    }
    const float4* tb = t4 + (size_t)b*64*plane;
    int px = blockIdx.x*16+tx, py = blockIdx.y*16+ty;
    size_t opix = (size_t)py*Ww+px;
    __syncthreads();
    for (int gi=0; gi<G_PER; gi++) {
        int g = g0 + gi;
        const float4* tg = tb + (size_t)g*plane;
        for (int i=tid;i<324;i+=256){
            int4 oo = so4[i];
            float4 r = make_float4(0.f,0.f,0.f,0.f);
            if (oo.x >= 0) {
                float4 wv = swt[i];
                float4 v00=tg[oo.x], v01=tg[oo.y], v10=tg[oo.z], v11=tg[oo.w];
                r.x=v00.x*wv.x+v01.x*wv.y+v10.x*wv.z+v11.x*wv.w;
                r.y=v00.y*wv.x+v01.y*wv.y+v10.y*wv.z+v11.y*wv.w;
                r.z=v00.z*wv.x+v01.z*wv.y+v10.z*wv.z+v11.z*wv.w;
                r.w=v00.w*wv.x+v01.w*wv.y+v10.w*wv.z+v11.w*wv.w;
            }
            td[i]=r;
        }
        __syncthreads();
        float wd[4][9];
        #pragma unroll
        for (int c=0;c<4;c++)
            #pragma unroll
            for (int k=0;k<9;k++) wd[c][k]=sdw[(gi*4+c)*9+k];
        float a0=0.f,a1=0.f,a2=0.f,a3=0.f;
        #pragma unroll
        for (int ky=0;ky<3;ky++)
            #pragma unroll
            for (int kx=0;kx<3;kx++){
                float4 v = td[(ty+ky)*18+tx+kx];
                int k = ky*3+kx;
                a0+=v.x*wd[0][k]; a1+=v.y*wd[1][k];
                a2+=v.z*wd[2][k]; a3+=v.w*wd[3][k];
            }
        float r0=fmaxf(a0,0.f), r1=fmaxf(a1,0.f), r2=fmaxf(a2,0.f), r3=fmaxf(a3,0.f);
        float4 p0=spw[gi*4],p1=spw[gi*4+1],p2=spw[gi*4+2],p3=spw[gi*4+3],wsv=sws[gi];
        float4 o;
        o.x=(r0*p0.x+r1*p0.y+r2*p0.z+r3*p0.w)*wsv.x;
        o.y=(r0*p1.x+r1*p1.y+r2*p1.z+r3*p1.w)*wsv.y;
        o.z=(r0*p2.x+r1*p2.y+r2*p2.z+r3*p2.w)*wsv.z;
        o.w=(r0*p3.x+r1*p3.y+r2*p3.z+r3*p3.w)*wsv.w;
        outp[((size_t)b*64+g)*plane + opix] = o;
        __syncthreads();
    }
}

// inverse Haar: interleaved coeff (h2,w2) -> plain (2h2,2w2)
__global__ void k_iwt(const float4* __restrict__ coef, float* __restrict__ outp,
                      int h2, int w2) {
    int idx = blockIdx.x*blockDim.x + threadIdx.x;
    int total = BB*CCH*h2*w2;
    if (idx >= total) return;
    int j = idx % w2; int t = idx / w2;
    int i = t % h2;  t /= h2;
    int c = t % CCH; int b = t / CCH;
    float4 v = coef[((size_t)(b*CCH+c)*h2 + i)*w2 + j];
    float LL=v.x, A=v.y, Bv=v.z, Cv=v.w;
    int Wo = 2*w2;
    float* o = outp + ((size_t)(b*CCH+c)*(2*h2) + 2*i)*Wo + 2*j;
    o[0]    = 0.5f*(LL+A+Bv+Cv);
    o[1]    = 0.5f*(LL+A-Bv-Cv);
    o[Wo]   = 0.5f*(LL-A+Bv-Cv);
    o[Wo+1] = 0.5f*(LL-A-Bv+Cv);
}

// final: level0 iwt + base depthwise conv + bias*scale + gamma add
__global__ void k_final(const float* __restrict__ x, const float4* __restrict__ coef,
                        const float* __restrict__ nxt, const float* __restrict__ bw,
                        const float* __restrict__ bb_, const float* __restrict__ bscale,
                        const float* __restrict__ gammap, float* __restrict__ outp) {
    int idx = blockIdx.x*blockDim.x + threadIdx.x;
    int total = BB*CCH*128*128;
    if (idx >= total) return;
    int j = idx % 128; int t = idx / 128;
    int i = t % 128; t /= 128;
    int c = t % CCH; int b = t / CCH;
    size_t ci = ((size_t)(b*CCH+c)*128 + i)*128 + j;
    float4 v = coef[ci];
    float LL = v.x + nxt[ci];
    float A=v.y, Bv=v.z, Cv=v.w;
    float rec[2][2];
    rec[0][0]=0.5f*(LL+A+Bv+Cv); rec[0][1]=0.5f*(LL+A-Bv-Cv);
    rec[1][0]=0.5f*(LL-A+Bv-Cv); rec[1][1]=0.5f*(LL-A-Bv+Cv);
    float gm = gammap[0];
    const float* xp = x + (size_t)(b*CCH+c)*256*256;
    float wreg[9];
    #pragma unroll
    for (int k=0;k<9;k++) wreg[k]=__ldg(&bw[c*9+k]);
    float bias=__ldg(&bb_[c]), sc=__ldg(&bscale[c]);
    float xv[4][4];
    #pragma unroll
    for (int dy=0;dy<4;dy++){
        int yy = 2*i-1+dy;
        #pragma unroll
        for (int dx=0;dx<4;dx++){
            int xx = 2*j-1+dx;
            xv[dy][dx] = (yy>=0&&yy<256&&xx>=0&&xx<256) ? xp[(size_t)yy*256+xx] : 0.f;
        }
    }
    float* op = outp + (size_t)(b*CCH+c)*256*256;
    #pragma unroll
    for (int ri=0;ri<2;ri++)
        #pragma unroll
        for (int rj=0;rj<2;rj++){
            float a = 0.f;
            #pragma unroll
            for (int ky=0;ky<3;ky++)
                #pragma unroll
                for (int kx=0;kx<3;kx++)
                    a += xv[ri+ky][rj+kx]*wreg[ky*3+kx];
            op[(size_t)(2*i+ri)*256 + 2*j+rj] = (a+bias)*sc + gm*rec[ri][rj];
        }
}

extern "C" void kernel_launch(void* const* d_in, const int* in_sizes, int n_in,
                              void* d_out, int out_size) {
    const float* x       = (const float*)d_in[0];
    const float* base_w  = (const float*)d_in[1];
    const float* base_b  = (const float*)d_in[2];
    const float* base_sc = (const float*)d_in[3];
    const float* off_w   = (const float*)d_in[4];
    const float* off_b   = (const float*)d_in[5];
    const float* dw_w    = (const float*)d_in[6];
    const float* pw_w    = (const float*)d_in[7];
    const float* wscale  = (const float*)d_in[8];
    const float* gamma   = (const float*)d_in[9];
    float* out = (float*)d_out;

    float4 *t0, *tpw0, *t1, *tpw1;
    float *ll1, *nxt1, *off0, *off1, *offacc;
    cudaGetSymbolAddress((void**)&t0,   g_t0);
    cudaGetSymbolAddress((void**)&tpw0, g_tpw0);
    cudaGetSymbolAddress((void**)&t1,   g_t1);
    cudaGetSymbolAddress((void**)&tpw1, g_tpw1);
    cudaGetSymbolAddress((void**)&ll1,  g_ll1);
    cudaGetSymbolAddress((void**)&nxt1, g_nxt1);
    cudaGetSymbolAddress((void**)&off0, g_off0);
    cudaGetSymbolAddress((void**)&off1, g_off1);
    cudaGetSymbolAddress((void**)&offacc, g_offacc);

    // level 0 analysis: x(256^2) -> t0(128^2 interleaved) + ll1
    k_wt<<<16384, 256>>>(x, t0, ll1, 256, 256, (size_t)256*256, (size_t)64*256*256);
    // level 0 offsets
    k_off2<<<dim3(4,4,32), dim3(32,8)>>>(t0, off_w, offacc, 128, 128);
    k_offfin<<<256, 256>>>(offacc, off_b, off0, 128, 128);
    // level 0 snake+pw
    k_sdp<<<dim3(8,8,32), dim3(16,16)>>>(t0, off0, dw_w, pw_w, wscale, tpw0, 128, 128);
    // level 1 analysis: ll1(128^2) -> t1(64^2 interleaved)
    k_wt<<<4096, 256>>>(ll1, (float4*)t1, nullptr, 128, 128, (size_t)128*128, (size_t)64*128*128);
    // level 1 offsets
    k_off2<<<dim3(2,2,32), dim3(32,8)>>>(t1, off_w + 2*256*9, offacc, 64, 64);
    k_offfin<<<64, 256>>>(offacc, off_b + 2, off1, 64, 64);
    // level 1 snake+pw
    k_sdp<<<dim3(4,4,32), dim3(16,16)>>>(t1, off1, dw_w + 256*9, pw_w + 256*4,
                                         wscale + 256, tpw1, 64, 64);
    // level 1 inverse
    k_iwt<<<4096, 256>>>(tpw1, nxt1, 64, 64);
    // final fused
    k_final<<<16384, 256>>>(x, tpw0, nxt1, base_w, base_b, base_sc, gamma, out);
}

// round 5
// speedup vs baseline: 1.5428x; 1.0306x over previous
#include <cuda_runtime.h>
#include <math.h>

#define BB 4
#define CCH 64
#define G_PER 8

__device__ __align__(16) float g_t0  [(size_t)4*64*128*128*4];
__device__ __align__(16) float g_tpw0[(size_t)4*64*128*128*4];
__device__ __align__(16) float g_t1  [(size_t)4*64*64*64*4];
__device__ __align__(16) float g_tpw1[(size_t)4*64*64*64*4];
__device__ float g_ll1 [(size_t)4*64*128*128];
__device__ __align__(8) float g_off0[(size_t)4*2*128*128];
__device__ __align__(8) float g_off1[(size_t)4*2*64*64];
__device__ float g_offacc[(size_t)8*4*2*128*128];

// Haar analysis: plain src -> interleaved dst (b,c,h2,w2,4); optional LL copy
__global__ void k_wt(const float* __restrict__ src, float4* __restrict__ dst,
                     float* __restrict__ llout, int Hs, int Ws,
                     size_t chStep, size_t bStride) {
    int h2 = Hs >> 1, w2 = Ws >> 1;
    int idx = blockIdx.x * blockDim.x + threadIdx.x;
    int total = BB * CCH * h2 * w2;
    if (idx >= total) return;
    int q = idx % w2; int t = idx / w2;
    int p = t % h2;  t /= h2;
    int g = t % CCH; int b = t / CCH;
    const float* s = src + (size_t)b*bStride + (size_t)g*chStep + (size_t)(2*p)*Ws + 2*q;
    float x00=s[0], x01=s[1], x10=s[Ws], x11=s[Ws+1];
    float LL=0.5f*(x00+x01+x10+x11), A=0.5f*(x00+x01-x10-x11);
    float Bv=0.5f*(x00-x01+x10-x11), Cv=0.5f*(x00-x01-x10+x11);
    size_t o = ((size_t)(b*CCH+g)*h2 + p)*w2 + q;
    dst[o] = make_float4(LL,A,Bv,Cv);
    if (llout) llout[o] = LL;
}

// dense 3x3 conv 256->2, 8-way channel-split partials. grid(W/32,H/32,B*8) block(32,8)
__global__ void k_off2(const float4* __restrict__ t4, const float* __restrict__ ow,
                       float* __restrict__ acc, int Hh, int Ww) {
    __shared__ float wsm[576];
    __shared__ float tile[8][34][34];
    int tx=threadIdx.x, ty=threadIdx.y, tid=ty*32+tx;
    int split = blockIdx.z & 7, b = blockIdx.z >> 3;
    int cb = split*32, gb = split*8;
    for (int i=tid;i<576;i+=256){int o=i/288,rem=i%288;wsm[i]=ow[(o*256+cb+rem/9)*9+rem%9];}
    size_t plane = (size_t)Hh*Ww;
    const float4* tb = t4 + (size_t)b*64*plane;
    int gx0 = blockIdx.x*32-1, gy0 = blockIdx.y*32-1;
    float a0[4]={0,0,0,0}, a1[4]={0,0,0,0};
    for (int gg=0; gg<8; gg+=2) {
        __syncthreads();
        for (int i=tid;i<2*1156;i+=256){
            int g2=i/1156,pos=i%1156,yy=pos/34,xx=pos%34;
            int gy=gy0+yy, gx=gx0+xx;
            float4 v = make_float4(0.f,0.f,0.f,0.f);
            if (gy>=0&&gy<Hh&&gx>=0&&gx<Ww) v = tb[(size_t)(gb+gg+g2)*plane+(size_t)gy*Ww+gx];
            tile[g2*4+0][yy][xx]=v.x; tile[g2*4+1][yy][xx]=v.y;
            tile[g2*4+2][yy][xx]=v.z; tile[g2*4+3][yy][xx]=v.w;
        }
        __syncthreads();
        #pragma unroll
        for (int c8=0;c8<8;c8++){
            int lc = gg*4 + c8;
            float w0[9], w1[9];
            #pragma unroll
            for (int k=0;k<9;k++){w0[k]=wsm[lc*9+k];w1[k]=wsm[288+lc*9+k];}
            float vals[6][3];
            #pragma unroll
            for (int rr=0;rr<6;rr++)
                #pragma unroll
                for (int kx=0;kx<3;kx++) vals[rr][kx]=tile[c8][4*ty+rr][tx+kx];
            #pragma unroll
            for (int r=0;r<4;r++)
                #pragma unroll
                for (int ky=0;ky<3;ky++)
                    #pragma unroll
                    for (int kx=0;kx<3;kx++){
                        float v=vals[r+ky][kx];
                        a0[r]+=v*w0[ky*3+kx]; a1[r]+=v*w1[ky*3+kx];
                    }
        }
    }
    float* ob = acc + (((size_t)split*4 + b)*2)*plane;
    int px = blockIdx.x*32+tx;
    #pragma unroll
    for (int r=0;r<4;r++){
        int py = blockIdx.y*32 + ty*4 + r;
        ob[(size_t)py*Ww+px]=a0[r];
        ob[plane+(size_t)py*Ww+px]=a1[r];
    }
}

__device__ __forceinline__ float reflect_clip(float v, float size) {
    float two = 2.f*size;
    float r = fmodf(v+0.5f, two);
    if (r < 0.f) r += two;
    if (r > size) r = two - r;
    r -= 0.5f;
    return fminf(fmaxf(r, 0.f), size-1.f);
}

// sum 8 partials + bias -> tanh -> reflect-clipped coords, packed float2
__global__ void k_offfin(const float* __restrict__ acc, const float* __restrict__ ob,
                         float2* __restrict__ offmap, int Hh, int Ww) {
    int idx = blockIdx.x*blockDim.x + threadIdx.x;
    int n = BB*Hh*Ww;
    if (idx >= n) return;
    int px = idx % Ww; int t = idx / Ww;
    int py = t % Hh; int b = t / Hh;
    size_t plane = (size_t)Hh*Ww, pix = (size_t)py*Ww+px;
    float s0=0.f, s1=0.f;
    #pragma unroll
    for (int s=0;s<8;s++){
        const float* base = acc + (((size_t)s*4+b)*2)*plane + pix;
        s0 += base[0]; s1 += base[plane];
    }
    float offx = tanhf(s0 + ob[0]);
    float offy = tanhf(s1 + ob[1]);
    float w = (float)Ww, h = (float)Hh;
    float ix = ((float)px + offx) * (w/(w-1.f)) - 0.5f;
    float iy = ((float)py + offy) * (h/(h-1.f)) - 0.5f;
    offmap[(size_t)b*plane + pix] = make_float2(reflect_clip(ix, w), reflect_clip(iy, h));
}

// fused grid_sample + depthwise3x3 + relu + grouped1x1 + wscale.
// block(32,8): tile 32x16 outputs, 2 vertical outputs/thread. grid(W/32,H/16,B*8)
__global__ void k_sdp(const float4* __restrict__ t4, const float2* __restrict__ offmap,
                      const float* __restrict__ dww, const float* __restrict__ pww,
                      const float* __restrict__ wsc, float4* __restrict__ outp,
                      int Hh, int Ww) {
    __shared__ __align__(8) float2 sxy[612];     // 34x18 halo coords
    __shared__ __align__(16) float4 td[612];
    __shared__ float  sdw[G_PER*36];
    __shared__ float4 spw[G_PER*4];
    __shared__ float4 sws[G_PER];
    int tx=threadIdx.x, ty=threadIdx.y, tid=ty*32+tx;
    int b = blockIdx.z >> 3, g0 = (blockIdx.z & 7)*G_PER;
    for (int i=tid;i<G_PER*36;i+=256) sdw[i] = dww[g0*36 + i];
    if (tid < G_PER*4) spw[tid] = *(const float4*)&pww[(g0*4+tid)*4];
    if (tid < G_PER)   sws[tid] = *(const float4*)&wsc[(g0+tid)*4];
    size_t plane = (size_t)Hh*Ww;
    const float2* ofp = offmap + (size_t)b*plane;
    int gx0 = blockIdx.x*32-1, gy0 = blockIdx.y*16-1;
    for (int i=tid;i<612;i+=256){
        int xx=i%34, yy=i/34;
        int gx=gx0+xx, gy=gy0+yy;
        float2 v = make_float2(-1.f, 0.f);
        if (gx>=0&&gx<Ww&&gy>=0&&gy<Hh) v = ofp[(size_t)gy*Ww+gx];
        sxy[i]=v;
    }
    const float4* tb = t4 + (size_t)b*64*plane;
    int px = blockIdx.x*32+tx, py0 = blockIdx.y*16 + 2*ty;
    __syncthreads();
    for (int gi=0; gi<G_PER; gi++) {
        int g = g0 + gi;
        const float4* tg = tb + (size_t)g*plane;
        for (int i=tid;i<612;i+=256){
            float2 c = sxy[i];
            float4 r = make_float4(0.f,0.f,0.f,0.f);
            if (c.x >= 0.f) {
                float x0=floorf(c.x), y0=floorf(c.y);
                float wx=c.x-x0, wy=c.y-y0;
                int x0i=(int)x0, y0i=(int)y0;
                int x1i=min(x0i+1,Ww-1), y1i=min(y0i+1,Hh-1);
                float4 v00=tg[(size_t)y0i*Ww+x0i], v01=tg[(size_t)y0i*Ww+x1i];
                float4 v10=tg[(size_t)y1i*Ww+x0i], v11=tg[(size_t)y1i*Ww+x1i];
                float w00=(1.f-wy)*(1.f-wx), w01=(1.f-wy)*wx;
                float w10=wy*(1.f-wx), w11=wy*wx;
                r.x=v00.x*w00+v01.x*w01+v10.x*w10+v11.x*w11;
                r.y=v00.y*w00+v01.y*w01+v10.y*w10+v11.y*w11;
                r.z=v00.z*w00+v01.z*w01+v10.z*w10+v11.z*w11;
                r.w=v00.w*w00+v01.w*w01+v10.w*w10+v11.w*w11;
            }
            td[i]=r;
        }
        __syncthreads();
        float wd[4][9];
        #pragma unroll
        for (int c=0;c<4;c++)
            #pragma unroll
            for (int k=0;k<9;k++) wd[c][k]=sdw[(gi*4+c)*9+k];
        float acc0[4]={0,0,0,0}, acc1[4]={0,0,0,0};
        #pragma unroll
        for (int ky=0; ky<4; ky++){
            const float4* trow = &td[(2*ty+ky)*34 + tx];
            float4 v0=trow[0], v1=trow[1], v2=trow[2];
            if (ky < 3) {          // output row 0, kernel row ky
                int kb = ky*3;
                #pragma unroll
                for (int c=0;c<4;c++){
                    float w0=wd[c][kb],w1=wd[c][kb+1],w2=wd[c][kb+2];
                    float vv0 = c==0?v0.x:c==1?v0.y:c==2?v0.z:v0.w;
                    float vv1 = c==0?v1.x:c==1?v1.y:c==2?v1.z:v1.w;
                    float vv2 = c==0?v2.x:c==1?v2.y:c==2?v2.z:v2.w;
                    acc0[c] += vv0*w0 + vv1*w1 + vv2*w2;
                }
            }
            if (ky >= 1) {         // output row 1, kernel row ky-1
                int kb = (ky-1)*3;
                #pragma unroll
                for (int c=0;c<4;c++){
                    float w0=wd[c][kb],w1=wd[c][kb+1],w2=wd[c][kb+2];
                    float vv0 = c==0?v0.x:c==1?v0.y:c==2?v0.z:v0.w;
                    float vv1 = c==0?v1.x:c==1?v1.y:c==2?v1.z:v1.w;
                    float vv2 = c==0?v2.x:c==1?v2.y:c==2?v2.z:v2.w;
                    acc1[c] += vv0*w0 + vv1*w1 + vv2*w2;
                }
            }
        }
        float4 p0=spw[gi*4],p1=spw[gi*4+1],p2=spw[gi*4+2],p3=spw[gi*4+3],wsv=sws[gi];
        float4* og = outp + ((size_t)b*64+g)*plane;
        #pragma unroll
        for (int r=0;r<2;r++){
            float* ac = r ? acc1 : acc0;
            float r0=fmaxf(ac[0],0.f), r1=fmaxf(ac[1],0.f);
            float r2=fmaxf(ac[2],0.f), r3=fmaxf(ac[3],0.f);
            float4 o;
            o.x=(r0*p0.x+r1*p0.y+r2*p0.z+r3*p0.w)*wsv.x;
            o.y=(r0*p1.x+r1*p1.y+r2*p1.z+r3*p1.w)*wsv.y;
            o.z=(r0*p2.x+r1*p2.y+r2*p2.z+r3*p2.w)*wsv.z;
            o.w=(r0*p3.x+r1*p3.y+r2*p3.z+r3*p3.w)*wsv.w;
            og[(size_t)(py0+r)*Ww + px] = o;
        }
        __syncthreads();
    }
}

// final: level1 iwt (on the fly) + level0 iwt + base depthwise conv + bias*scale + gamma
__global__ void k_final(const float* __restrict__ x, const float4* __restrict__ coef,
                        const float4* __restrict__ tpw1, const float* __restrict__ bw,
                        const float* __restrict__ bb_, const float* __restrict__ bscale,
                        const float* __restrict__ gammap, float* __restrict__ outp) {
    int idx = blockIdx.x*blockDim.x + threadIdx.x;
    int total = BB*CCH*128*128;
    if (idx >= total) return;
    int j = idx % 128; int t = idx / 128;
    int i = t % 128; t /= 128;
    int c = t % CCH; int b = t / CCH;
    size_t ci = ((size_t)(b*CCH+c)*128 + i)*128 + j;
    // nxt value: inverse level-1 Haar of tpw1 at (i>>1, j>>1), parity (i&1, j&1)
    float4 n = tpw1[((size_t)(b*CCH+c)*64 + (i>>1))*64 + (j>>1)];
    float sA = (i&1)? -1.f : 1.f;
    float sB = (j&1)? -1.f : 1.f;
    float nxtv = 0.5f*(n.x + sA*n.y + sB*n.z + sA*sB*n.w);
    float4 v = coef[ci];
    float LL = v.x + nxtv;
    float A=v.y, Bv=v.z, Cv=v.w;
    float rec[2][2];
    rec[0][0]=0.5f*(LL+A+Bv+Cv); rec[0][1]=0.5f*(LL+A-Bv-Cv);
    rec[1][0]=0.5f*(LL-A+Bv-Cv); rec[1][1]=0.5f*(LL-A-Bv+Cv);
    float gm = gammap[0];
    const float* xp = x + (size_t)(b*CCH+c)*256*256;
    float wreg[9];
    #pragma unroll
    for (int k=0;k<9;k++) wreg[k]=__ldg(&bw[c*9+k]);
    float bias=__ldg(&bb_[c]), sc=__ldg(&bscale[c]);
    float xv[4][4];
    #pragma unroll
    for (int dy=0;dy<4;dy++){
        int yy = 2*i-1+dy;
        #pragma unroll
        for (int dx=0;dx<4;dx++){
            int xx = 2*j-1+dx;
            xv[dy][dx] = (yy>=0&&yy<256&&xx>=0&&xx<256) ? xp[(size_t)yy*256+xx] : 0.f;
        }
    }
    float* op = outp + (size_t)(b*CCH+c)*256*256;
    #pragma unroll
    for (int ri=0;ri<2;ri++)
        #pragma unroll
        for (int rj=0;rj<2;rj++){
            float a = 0.f;
            #pragma unroll
            for (int ky=0;ky<3;ky++)
                #pragma unroll
                for (int kx=0;kx<3;kx++)
                    a += xv[ri+ky][rj+kx]*wreg[ky*3+kx];
            op[(size_t)(2*i+ri)*256 + 2*j+rj] = (a+bias)*sc + gm*rec[ri][rj];
        }
}

extern "C" void kernel_launch(void* const* d_in, const int* in_sizes, int n_in,
                              void* d_out, int out_size) {
    const float* x       = (const float*)d_in[0];
    const float* base_w  = (const float*)d_in[1];
    const float* base_b  = (const float*)d_in[2];
    const float* base_sc = (const float*)d_in[3];
    const float* off_w   = (const float*)d_in[4];
    const float* off_b   = (const float*)d_in[5];
    const float* dw_w    = (const float*)d_in[6];
    const float* pw_w    = (const float*)d_in[7];
    const float* wscale  = (const float*)d_in[8];
    const float* gamma   = (const float*)d_in[9];
    float* out = (float*)d_out;

    float4 *t0, *tpw0, *t1, *tpw1;
    float *ll1, *off0, *off1, *offacc;
    cudaGetSymbolAddress((void**)&t0,   g_t0);
    cudaGetSymbolAddress((void**)&tpw0, g_tpw0);
    cudaGetSymbolAddress((void**)&t1,   g_t1);
    cudaGetSymbolAddress((void**)&tpw1, g_tpw1);
    cudaGetSymbolAddress((void**)&ll1,  g_ll1);
    cudaGetSymbolAddress((void**)&off0, g_off0);
    cudaGetSymbolAddress((void**)&off1, g_off1);
    cudaGetSymbolAddress((void**)&offacc, g_offacc);

    // level 0
    k_wt<<<16384, 256>>>(x, t0, ll1, 256, 256, (size_t)256*256, (size_t)64*256*256);
    k_off2<<<dim3(4,4,32), dim3(32,8)>>>(t0, off_w, offacc, 128, 128);
    k_offfin<<<256, 256>>>(offacc, off_b, (float2*)off0, 128, 128);
    k_sdp<<<dim3(4,8,32), dim3(32,8)>>>(t0, (const float2*)off0, dw_w, pw_w, wscale,
                                        tpw0, 128, 128);
    // level 1
    k_wt<<<4096, 256>>>(ll1, t1, nullptr, 128, 128, (size_t)128*128, (size_t)64*128*128);
    k_off2<<<dim3(2,2,32), dim3(32,8)>>>(t1, off_w + 2*256*9, offacc, 64, 64);
    k_offfin<<<64, 256>>>(offacc, off_b + 2, (float2*)off1, 64, 64);
    k_sdp<<<dim3(2,4,32), dim3(32,8)>>>(t1, (const float2*)off1, dw_w + 256*9,
                                        pw_w + 256*4, wscale + 256, tpw1, 64, 64);
    // reconstruction + base, fused
    k_final<<<16384, 256>>>(x, tpw0, tpw1, base_w, base_b, base_sc, gamma, out);
}

// round 6
// speedup vs baseline: 1.5545x; 1.0076x over previous
#include <cuda_runtime.h>
#include <math.h>

#define BB 4
#define CCH 64
#define G_PER 8

__device__ __align__(16) float g_t0  [(size_t)4*64*128*128*4];
__device__ __align__(16) float g_tpw0[(size_t)4*64*128*128*4];
__device__ __align__(16) float g_t1  [(size_t)4*64*64*64*4];
__device__ __align__(16) float g_tpw1[(size_t)4*64*64*64*4];
__device__ float g_ll1 [(size_t)4*64*128*128];
__device__ __align__(8) float g_off0[(size_t)4*2*128*128];
__device__ __align__(8) float g_off1[(size_t)4*2*64*64];
__device__ float g_offacc[(size_t)8*4*2*128*128];

// Haar analysis: plain src -> interleaved dst (b,c,h2,w2,4); optional LL copy
__global__ void k_wt(const float* __restrict__ src, float4* __restrict__ dst,
                     float* __restrict__ llout, int Hs, int Ws,
                     size_t chStep, size_t bStride) {
    int h2 = Hs >> 1, w2 = Ws >> 1;
    int idx = blockIdx.x * blockDim.x + threadIdx.x;
    int total = BB * CCH * h2 * w2;
    if (idx >= total) return;
    int q = idx % w2; int t = idx / w2;
    int p = t % h2;  t /= h2;
    int g = t % CCH; int b = t / CCH;
    const float* s = src + (size_t)b*bStride + (size_t)g*chStep + (size_t)(2*p)*Ws + 2*q;
    float x00=s[0], x01=s[1], x10=s[Ws], x11=s[Ws+1];
    float LL=0.5f*(x00+x01+x10+x11), A=0.5f*(x00+x01-x10-x11);
    float Bv=0.5f*(x00-x01+x10-x11), Cv=0.5f*(x00-x01-x10+x11);
    size_t o = ((size_t)(b*CCH+g)*h2 + p)*w2 + q;
    dst[o] = make_float4(LL,A,Bv,Cv);
    if (llout) llout[o] = LL;
}

// dense 3x3 conv 256->2, 8-way channel-split partials. grid(W/32,H/32,B*8) block(32,8)
__global__ void k_off2(const float4* __restrict__ t4, const float* __restrict__ ow,
                       float* __restrict__ acc, int Hh, int Ww) {
    __shared__ float wsm[576];
    __shared__ float tile[8][34][34];
    int tx=threadIdx.x, ty=threadIdx.y, tid=ty*32+tx;
    int split = blockIdx.z & 7, b = blockIdx.z >> 3;
    int cb = split*32, gb = split*8;
    for (int i=tid;i<576;i+=256){int o=i/288,rem=i%288;wsm[i]=ow[(o*256+cb+rem/9)*9+rem%9];}
    size_t plane = (size_t)Hh*Ww;
    const float4* tb = t4 + (size_t)b*64*plane;
    int gx0 = blockIdx.x*32-1, gy0 = blockIdx.y*32-1;
    float a0[4]={0,0,0,0}, a1[4]={0,0,0,0};
    for (int gg=0; gg<8; gg+=2) {
        __syncthreads();
        for (int i=tid;i<2*1156;i+=256){
            int g2=i/1156,pos=i%1156,yy=pos/34,xx=pos%34;
            int gy=gy0+yy, gx=gx0+xx;
            float4 v = make_float4(0.f,0.f,0.f,0.f);
            if (gy>=0&&gy<Hh&&gx>=0&&gx<Ww) v = tb[(size_t)(gb+gg+g2)*plane+(size_t)gy*Ww+gx];
            tile[g2*4+0][yy][xx]=v.x; tile[g2*4+1][yy][xx]=v.y;
            tile[g2*4+2][yy][xx]=v.z; tile[g2*4+3][yy][xx]=v.w;
        }
        __syncthreads();
        #pragma unroll
        for (int c8=0;c8<8;c8++){
            int lc = gg*4 + c8;
            float w0[9], w1[9];
            #pragma unroll
            for (int k=0;k<9;k++){w0[k]=wsm[lc*9+k];w1[k]=wsm[288+lc*9+k];}
            float vals[6][3];
            #pragma unroll
            for (int rr=0;rr<6;rr++)
                #pragma unroll
                for (int kx=0;kx<3;kx++) vals[rr][kx]=tile[c8][4*ty+rr][tx+kx];
            #pragma unroll
            for (int r=0;r<4;r++)
                #pragma unroll
                for (int ky=0;ky<3;ky++)
                    #pragma unroll
                    for (int kx=0;kx<3;kx++){
                        float v=vals[r+ky][kx];
                        a0[r]+=v*w0[ky*3+kx]; a1[r]+=v*w1[ky*3+kx];
                    }
        }
    }
    float* ob = acc + (((size_t)split*4 + b)*2)*plane;
    int px = blockIdx.x*32+tx;
    #pragma unroll
    for (int r=0;r<4;r++){
        int py = blockIdx.y*32 + ty*4 + r;
        ob[(size_t)py*Ww+px]=a0[r];
        ob[plane+(size_t)py*Ww+px]=a1[r];
    }
}

__device__ __forceinline__ float reflect_clip(float v, float size) {
    float two = 2.f*size;
    float r = fmodf(v+0.5f, two);
    if (r < 0.f) r += two;
    if (r > size) r = two - r;
    r -= 0.5f;
    return fminf(fmaxf(r, 0.f), size-1.f);
}

// sum 8 partials + bias -> tanh -> reflect-clipped coords, packed float2
__global__ void k_offfin(const float* __restrict__ acc, const float* __restrict__ ob,
                         float2* __restrict__ offmap, int Hh, int Ww) {
    int idx = blockIdx.x*blockDim.x + threadIdx.x;
    int n = BB*Hh*Ww;
    if (idx >= n) return;
    int px = idx % Ww; int t = idx / Ww;
    int py = t % Hh; int b = t / Hh;
    size_t plane = (size_t)Hh*Ww, pix = (size_t)py*Ww+px;
    float s0=0.f, s1=0.f;
    #pragma unroll
    for (int s=0;s<8;s++){
        const float* base = acc + (((size_t)s*4+b)*2)*plane + pix;
        s0 += base[0]; s1 += base[plane];
    }
    float offx = tanhf(s0 + ob[0]);
    float offy = tanhf(s1 + ob[1]);
    float w = (float)Ww, h = (float)Hh;
    float ix = ((float)px + offx) * (w/(w-1.f)) - 0.5f;
    float iy = ((float)py + offy) * (h/(h-1.f)) - 0.5f;
    offmap[(size_t)b*plane + pix] = make_float2(reflect_clip(ix, w), reflect_clip(iy, h));
}

// fused grid_sample + depthwise3x3 + relu + grouped1x1 + wscale.
// block(32,8): tile 32x16 outputs, 2 vertical outputs/thread. grid(W/32,H/16,B*8)
__global__ void k_sdp(const float4* __restrict__ t4, const float2* __restrict__ offmap,
                      const float* __restrict__ dww, const float* __restrict__ pww,
                      const float* __restrict__ wsc, float4* __restrict__ outp,
                      int Hh, int Ww) {
    __shared__ __align__(8) float2 sxy[612];     // 34x18 halo coords
    __shared__ __align__(16) float4 td[612];
    __shared__ float  sdw[G_PER*36];
    __shared__ float4 spw[G_PER*4];
    __shared__ float4 sws[G_PER];
    int tx=threadIdx.x, ty=threadIdx.y, tid=ty*32+tx;
    int b = blockIdx.z >> 3, g0 = (blockIdx.z & 7)*G_PER;
    for (int i=tid;i<G_PER*36;i+=256) sdw[i] = dww[g0*36 + i];
    if (tid < G_PER*4) spw[tid] = *(const float4*)&pww[(g0*4+tid)*4];
    if (tid < G_PER)   sws[tid] = *(const float4*)&wsc[(g0+tid)*4];
    size_t plane = (size_t)Hh*Ww;
    const float2* ofp = offmap + (size_t)b*plane;
    int gx0 = blockIdx.x*32-1, gy0 = blockIdx.y*16-1;
    for (int i=tid;i<612;i+=256){
        int xx=i%34, yy=i/34;
        int gx=gx0+xx, gy=gy0+yy;
        float2 v = make_float2(-1.f, 0.f);
        if (gx>=0&&gx<Ww&&gy>=0&&gy<Hh) v = ofp[(size_t)gy*Ww+gx];
        sxy[i]=v;
    }
    const float4* tb = t4 + (size_t)b*64*plane;
    int px = blockIdx.x*32+tx, py0 = blockIdx.y*16 + 2*ty;
    __syncthreads();
    for (int gi=0; gi<G_PER; gi++) {
        int g = g0 + gi;
        const float4* tg = tb + (size_t)g*plane;
        for (int i=tid;i<612;i+=256){
            float2 c = sxy[i];
            float4 r = make_float4(0.f,0.f,0.f,0.f);
            if (c.x >= 0.f) {
                float x0=floorf(c.x), y0=floorf(c.y);
                float wx=c.x-x0, wy=c.y-y0;
                int x0i=(int)x0, y0i=(int)y0;
                int x1i=min(x0i+1,Ww-1), y1i=min(y0i+1,Hh-1);
                float4 v00=tg[(size_t)y0i*Ww+x0i], v01=tg[(size_t)y0i*Ww+x1i];
                float4 v10=tg[(size_t)y1i*Ww+x0i], v11=tg[(size_t)y1i*Ww+x1i];
                float w00=(1.f-wy)*(1.f-wx), w01=(1.f-wy)*wx;
                float w10=wy*(1.f-wx), w11=wy*wx;
                r.x=v00.x*w00+v01.x*w01+v10.x*w10+v11.x*w11;
                r.y=v00.y*w00+v01.y*w01+v10.y*w10+v11.y*w11;
                r.z=v00.z*w00+v01.z*w01+v10.z*w10+v11.z*w11;
                r.w=v00.w*w00+v01.w*w01+v10.w*w10+v11.w*w11;
            }
            td[i]=r;
        }
        __syncthreads();
        float wd[4][9];
        #pragma unroll
        for (int c=0;c<4;c++)
            #pragma unroll
            for (int k=0;k<9;k++) wd[c][k]=sdw[(gi*4+c)*9+k];
        float acc0[4]={0,0,0,0}, acc1[4]={0,0,0,0};
        #pragma unroll
        for (int ky=0; ky<4; ky++){
            const float4* trow = &td[(2*ty+ky)*34 + tx];
            float4 v0=trow[0], v1=trow[1], v2=trow[2];
            if (ky < 3) {          // output row 0, kernel row ky
                int kb = ky*3;
                #pragma unroll
                for (int c=0;c<4;c++){
                    float w0=wd[c][kb],w1=wd[c][kb+1],w2=wd[c][kb+2];
                    float vv0 = c==0?v0.x:c==1?v0.y:c==2?v0.z:v0.w;
                    float vv1 = c==0?v1.x:c==1?v1.y:c==2?v1.z:v1.w;
                    float vv2 = c==0?v2.x:c==1?v2.y:c==2?v2.z:v2.w;
                    acc0[c] += vv0*w0 + vv1*w1 + vv2*w2;
                }
            }
            if (ky >= 1) {         // output row 1, kernel row ky-1
                int kb = (ky-1)*3;
                #pragma unroll
                for (int c=0;c<4;c++){
                    float w0=wd[c][kb],w1=wd[c][kb+1],w2=wd[c][kb+2];
                    float vv0 = c==0?v0.x:c==1?v0.y:c==2?v0.z:v0.w;
                    float vv1 = c==0?v1.x:c==1?v1.y:c==2?v1.z:v1.w;
                    float vv2 = c==0?v2.x:c==1?v2.y:c==2?v2.z:v2.w;
                    acc1[c] += vv0*w0 + vv1*w1 + vv2*w2;
                }
            }
        }
        float4 p0=spw[gi*4],p1=spw[gi*4+1],p2=spw[gi*4+2],p3=spw[gi*4+3],wsv=sws[gi];
        float4* og = outp + ((size_t)b*64+g)*plane;
        #pragma unroll
        for (int r=0;r<2;r++){
            float* ac = r ? acc1 : acc0;
            float r0=fmaxf(ac[0],0.f), r1=fmaxf(ac[1],0.f);
            float r2=fmaxf(ac[2],0.f), r3=fmaxf(ac[3],0.f);
            float4 o;
            o.x=(r0*p0.x+r1*p0.y+r2*p0.z+r3*p0.w)*wsv.x;
            o.y=(r0*p1.x+r1*p1.y+r2*p1.z+r3*p1.w)*wsv.y;
            o.z=(r0*p2.x+r1*p2.y+r2*p2.z+r3*p2.w)*wsv.z;
            o.w=(r0*p3.x+r1*p3.y+r2*p3.z+r3*p3.w)*wsv.w;
            og[(size_t)(py0+r)*Ww + px] = o;
        }
        __syncthreads();
    }
}

// final: level1 iwt (on the fly) + level0 iwt + base depthwise conv + bias*scale + gamma
__global__ void k_final(const float* __restrict__ x, const float4* __restrict__ coef,
                        const float4* __restrict__ tpw1, const float* __restrict__ bw,
                        const float* __restrict__ bb_, const float* __restrict__ bscale,
                        const float* __restrict__ gammap, float* __restrict__ outp) {
    int idx = blockIdx.x*blockDim.x + threadIdx.x;
    int total = BB*CCH*128*128;
    if (idx >= total) return;
    int j = idx % 128; int t = idx / 128;
    int i = t % 128; t /= 128;
    int c = t % CCH; int b = t / CCH;
    size_t ci = ((size_t)(b*CCH+c)*128 + i)*128 + j;
    // nxt value: inverse level-1 Haar of tpw1 at (i>>1, j>>1), parity (i&1, j&1)
    float4 n = tpw1[((size_t)(b*CCH+c)*64 + (i>>1))*64 + (j>>1)];
    float sA = (i&1)? -1.f : 1.f;
    float sB = (j&1)? -1.f : 1.f;
    float nxtv = 0.5f*(n.x + sA*n.y + sB*n.z + sA*sB*n.w);
    float4 v = coef[ci];
    float LL = v.x + nxtv;
    float A=v.y, Bv=v.z, Cv=v.w;
    float rec[2][2];
    rec[0][0]=0.5f*(LL+A+Bv+Cv); rec[0][1]=0.5f*(LL+A-Bv-Cv);
    rec[1][0]=0.5f*(LL-A+Bv-Cv); rec[1][1]=0.5f*(LL-A-Bv+Cv);
    float gm = gammap[0];
    const float* xp = x + (size_t)(b*CCH+c)*256*256;
    float wreg[9];
    #pragma unroll
    for (int k=0;k<9;k++) wreg[k]=__ldg(&bw[c*9+k]);
    float bias=__ldg(&bb_[c]), sc=__ldg(&bscale[c]);
    float xv[4][4];
    #pragma unroll
    for (int dy=0;dy<4;dy++){
        int yy = 2*i-1+dy;
        #pragma unroll
        for (int dx=0;dx<4;dx++){
            int xx = 2*j-1+dx;
            xv[dy][dx] = (yy>=0&&yy<256&&xx>=0&&xx<256) ? xp[(size_t)yy*256+xx] : 0.f;
        }
    }
    float* op = outp + (size_t)(b*CCH+c)*256*256;
    #pragma unroll
    for (int ri=0;ri<2;ri++)
        #pragma unroll
        for (int rj=0;rj<2;rj++){
            float a = 0.f;
            #pragma unroll
            for (int ky=0;ky<3;ky++)
                #pragma unroll
                for (int kx=0;kx<3;kx++)
                    a += xv[ri+ky][rj+kx]*wreg[ky*3+kx];
            op[(size_t)(2*i+ri)*256 + 2*j+rj] = (a+bias)*sc + gm*rec[ri][rj];
        }
}

extern "C" void kernel_launch(void* const* d_in, const int* in_sizes, int n_in,
                              void* d_out, int out_size) {
    const float* x       = (const float*)d_in[0];
    const float* base_w  = (const float*)d_in[1];
    const float* base_b  = (const float*)d_in[2];
    const float* base_sc = (const float*)d_in[3];
    const float* off_w   = (const float*)d_in[4];
    const float* off_b   = (const float*)d_in[5];
    const float* dw_w    = (const float*)d_in[6];
    const float* pw_w    = (const float*)d_in[7];
    const float* wscale  = (const float*)d_in[8];
    const float* gamma   = (const float*)d_in[9];
    float* out = (float*)d_out;

    float4 *t0, *tpw0, *t1, *tpw1;
    float *ll1, *off0, *off1, *offacc;
    cudaGetSymbolAddress((void**)&t0,   g_t0);
    cudaGetSymbolAddress((void**)&tpw0, g_tpw0);
    cudaGetSymbolAddress((void**)&t1,   g_t1);
    cudaGetSymbolAddress((void**)&tpw1, g_tpw1);
    cudaGetSymbolAddress((void**)&ll1,  g_ll1);
    cudaGetSymbolAddress((void**)&off0, g_off0);
    cudaGetSymbolAddress((void**)&off1, g_off1);
    cudaGetSymbolAddress((void**)&offacc, g_offacc);

    // level 0
    k_wt<<<16384, 256>>>(x, t0, ll1, 256, 256, (size_t)256*256, (size_t)64*256*256);
    k_off2<<<dim3(4,4,32), dim3(32,8)>>>(t0, off_w, offacc, 128, 128);
    k_offfin<<<256, 256>>>(offacc, off_b, (float2*)off0, 128, 128);
    k_sdp<<<dim3(4,8,32), dim3(32,8)>>>(t0, (const float2*)off0, dw_w, pw_w, wscale,
                                        tpw0, 128, 128);
    // level 1
    k_wt<<<4096, 256>>>(ll1, t1, nullptr, 128, 128, (size_t)128*128, (size_t)64*128*128);
    k_off2<<<dim3(2,2,32), dim3(32,8)>>>(t1, off_w + 2*256*9, offacc, 64, 64);
    k_offfin<<<64, 256>>>(offacc, off_b + 2, (float2*)off1, 64, 64);
    k_sdp<<<dim3(2,4,32), dim3(32,8)>>>(t1, (const float2*)off1, dw_w + 256*9,
                                        pw_w + 256*4, wscale + 256, tpw1, 64, 64);
    // reconstruction + base, fused
    k_final<<<16384, 256>>>(x, tpw0, tpw1, base_w, base_b, base_sc, gamma, out);
}

// round 8
// speedup vs baseline: 1.6520x; 1.0627x over previous
#include <cuda_runtime.h>
#include <math.h>

#define BB 4
#define CCH 64
#define G_PER 4

__device__ __align__(16) float g_t0  [(size_t)4*64*128*128*4];
__device__ __align__(16) float g_tpw0[(size_t)4*64*128*128*4];
__device__ __align__(16) float g_t1  [(size_t)4*64*64*64*4];
__device__ __align__(16) float g_tpw1[(size_t)4*64*64*64*4];
__device__ float g_ll1 [(size_t)4*64*128*128];
__device__ __align__(8) float g_off0[(size_t)4*2*128*128];
__device__ __align__(8) float g_off1[(size_t)4*2*64*64];
__device__ float g_offacc[(size_t)8*4*2*128*128];

// Haar analysis: plain src -> interleaved dst (b,c,h2,w2,4); optional LL copy
__global__ void k_wt(const float* __restrict__ src, float4* __restrict__ dst,
                     float* __restrict__ llout, int Hs, int Ws,
                     size_t chStep, size_t bStride) {
    int h2 = Hs >> 1, w2 = Ws >> 1;
    int idx = blockIdx.x * blockDim.x + threadIdx.x;
    int total = BB * CCH * h2 * w2;
    if (idx >= total) return;
    int q = idx % w2; int t = idx / w2;
    int p = t % h2;  t /= h2;
    int g = t % CCH; int b = t / CCH;
    const float* s = src + (size_t)b*bStride + (size_t)g*chStep + (size_t)(2*p)*Ws + 2*q;
    float x00=s[0], x01=s[1], x10=s[Ws], x11=s[Ws+1];
    float LL=0.5f*(x00+x01+x10+x11), A=0.5f*(x00+x01-x10-x11);
    float Bv=0.5f*(x00-x01+x10-x11), Cv=0.5f*(x00-x01-x10+x11);
    size_t o = ((size_t)(b*CCH+g)*h2 + p)*w2 + q;
    dst[o] = make_float4(LL,A,Bv,Cv);
    if (llout) llout[o] = LL;
}

// dense 3x3 conv 256->2, 8-way channel-split partials. grid(W/32,H/32,B*8) block(32,8)
__global__ void k_off2(const float4* __restrict__ t4, const float* __restrict__ ow,
                       float* __restrict__ acc, int Hh, int Ww) {
    __shared__ float wsm[576];
    __shared__ float tile[8][34][34];
    int tx=threadIdx.x, ty=threadIdx.y, tid=ty*32+tx;
    int split = blockIdx.z & 7, b = blockIdx.z >> 3;
    int cb = split*32, gb = split*8;
    for (int i=tid;i<576;i+=256){int o=i/288,rem=i%288;wsm[i]=ow[(o*256+cb+rem/9)*9+rem%9];}
    size_t plane = (size_t)Hh*Ww;
    const float4* tb = t4 + (size_t)b*64*plane;
    int gx0 = blockIdx.x*32-1, gy0 = blockIdx.y*32-1;
    float a0[4]={0,0,0,0}, a1[4]={0,0,0,0};
    for (int gg=0; gg<8; gg+=2) {
        __syncthreads();
        for (int i=tid;i<2*1156;i+=256){
            int g2=i/1156,pos=i%1156,yy=pos/34,xx=pos%34;
            int gy=gy0+yy, gx=gx0+xx;
            float4 v = make_float4(0.f,0.f,0.f,0.f);
            if (gy>=0&&gy<Hh&&gx>=0&&gx<Ww) v = tb[(size_t)(gb+gg+g2)*plane+(size_t)gy*Ww+gx];
            tile[g2*4+0][yy][xx]=v.x; tile[g2*4+1][yy][xx]=v.y;
            tile[g2*4+2][yy][xx]=v.z; tile[g2*4+3][yy][xx]=v.w;
        }
        __syncthreads();
        #pragma unroll
        for (int c8=0;c8<8;c8++){
            int lc = gg*4 + c8;
            float w0[9], w1[9];
            #pragma unroll
            for (int k=0;k<9;k++){w0[k]=wsm[lc*9+k];w1[k]=wsm[288+lc*9+k];}
            float vals[6][3];
            #pragma unroll
            for (int rr=0;rr<6;rr++)
                #pragma unroll
                for (int kx=0;kx<3;kx++) vals[rr][kx]=tile[c8][4*ty+rr][tx+kx];
            #pragma unroll
            for (int r=0;r<4;r++)
                #pragma unroll
                for (int ky=0;ky<3;ky++)
                    #pragma unroll
                    for (int kx=0;kx<3;kx++){
                        float v=vals[r+ky][kx];
                        a0[r]+=v*w0[ky*3+kx]; a1[r]+=v*w1[ky*3+kx];
                    }
        }
    }
    float* ob = acc + (((size_t)split*4 + b)*2)*plane;
    int px = blockIdx.x*32+tx;
    #pragma unroll
    for (int r=0;r<4;r++){
        int py = blockIdx.y*32 + ty*4 + r;
        ob[(size_t)py*Ww+px]=a0[r];
        ob[plane+(size_t)py*Ww+px]=a1[r];
    }
}

__device__ __forceinline__ float reflect_clip(float v, float size) {
    float two = 2.f*size;
    float r = fmodf(v+0.5f, two);
    if (r < 0.f) r += two;
    if (r > size) r = two - r;
    r -= 0.5f;
    return fminf(fmaxf(r, 0.f), size-1.f);
}

// sum 8 partials + bias -> tanh -> reflect-clipped coords, packed float2
__global__ void k_offfin(const float* __restrict__ acc, const float* __restrict__ ob,
                         float2* __restrict__ offmap, int Hh, int Ww) {
    int idx = blockIdx.x*blockDim.x + threadIdx.x;
    int n = BB*Hh*Ww;
    if (idx >= n) return;
    int px = idx % Ww; int t = idx / Ww;
    int py = t % Hh; int b = t / Hh;
    size_t plane = (size_t)Hh*Ww, pix = (size_t)py*Ww+px;
    float s0=0.f, s1=0.f;
    #pragma unroll
    for (int s=0;s<8;s++){
        const float* base = acc + (((size_t)s*4+b)*2)*plane + pix;
        s0 += base[0]; s1 += base[plane];
    }
    float offx = tanhf(s0 + ob[0]);
    float offy = tanhf(s1 + ob[1]);
    float w = (float)Ww, h = (float)Hh;
    float ix = ((float)px + offx) * (w/(w-1.f)) - 0.5f;
    float iy = ((float)py + offy) * (h/(h-1.f)) - 0.5f;
    offmap[(size_t)b*plane + pix] = make_float2(reflect_clip(ix, w), reflect_clip(iy, h));
}

__device__ __forceinline__ void gather_tile(const float4* __restrict__ tg,
                                            const float2* sxy, float4* tdb,
                                            int tid, int Hh, int Ww) {
    for (int i=tid;i<612;i+=256){
        float2 c = sxy[i];
        float4 r = make_float4(0.f,0.f,0.f,0.f);
        if (c.x >= 0.f) {
            float x0=floorf(c.x), y0=floorf(c.y);
            float wx=c.x-x0, wy=c.y-y0;
            int x0i=(int)x0, y0i=(int)y0;
            int x1i=min(x0i+1,Ww-1), y1i=min(y0i+1,Hh-1);
            float4 v00=tg[(size_t)y0i*Ww+x0i], v01=tg[(size_t)y0i*Ww+x1i];
            float4 v10=tg[(size_t)y1i*Ww+x0i], v11=tg[(size_t)y1i*Ww+x1i];
            float w00=(1.f-wy)*(1.f-wx), w01=(1.f-wy)*wx;
            float w10=wy*(1.f-wx), w11=wy*wx;
            r.x=v00.x*w00+v01.x*w01+v10.x*w10+v11.x*w11;
            r.y=v00.y*w00+v01.y*w01+v10.y*w10+v11.y*w11;
            r.z=v00.z*w00+v01.z*w01+v10.z*w10+v11.z*w11;
            r.w=v00.w*w00+v01.w*w01+v10.w*w10+v11.w*w11;
        }
        tdb[i]=r;
    }
}

// fused grid_sample + depthwise3x3 + relu + grouped1x1 + wscale.
// block(32,8): tile 32x16 outputs, 2 vertical outputs/thread. grid(W/32,H/16,B*16)
// double-buffered td: gather group gi+1 overlaps depthwise of gi; one sync/group.
__global__ void __launch_bounds__(256, 4)
k_sdp(const float4* __restrict__ t4, const float2* __restrict__ offmap,
      const float* __restrict__ dww, const float* __restrict__ pww,
      const float* __restrict__ wsc, float4* __restrict__ outp,
      int Hh, int Ww) {
    __shared__ __align__(8) float2 sxy[612];       // 34x18 halo coords
    __shared__ __align__(16) float4 td[2][612];
    __shared__ float4 sdw4[G_PER*9];               // per-tap weights, (c0,c1,c2,c3)
    __shared__ float4 spw[G_PER*4];
    __shared__ float4 sws[G_PER];
    int tx=threadIdx.x, ty=threadIdx.y, tid=ty*32+tx;
    int b = blockIdx.z >> 4, g0 = (blockIdx.z & 15)*G_PER;
    if (tid < G_PER*9) {
        int gi = tid/9, k = tid%9, c4 = (g0+gi)*4;
        sdw4[tid] = make_float4(dww[(c4+0)*9+k], dww[(c4+1)*9+k],
                                dww[(c4+2)*9+k], dww[(c4+3)*9+k]);
    }
    if (tid < G_PER*4) spw[tid] = *(const float4*)&pww[(g0*4+tid)*4];
    if (tid < G_PER)   sws[tid] = *(const float4*)&wsc[(g0+tid)*4];
    size_t plane = (size_t)Hh*Ww;
    const float2* ofp = offmap + (size_t)b*plane;
    int gx0 = blockIdx.x*32-1, gy0 = blockIdx.y*16-1;
    for (int i=tid;i<612;i+=256){
        int xx=i%34, yy=i/34;
        int gx=gx0+xx, gy=gy0+yy;
        float2 v = make_float2(-1.f, 0.f);
        if (gx>=0&&gx<Ww&&gy>=0&&gy<Hh) v = ofp[(size_t)gy*Ww+gx];
        sxy[i]=v;
    }
    const float4* tb = t4 + (size_t)b*64*plane;
    int px = blockIdx.x*32+tx, py0 = blockIdx.y*16 + 2*ty;
    __syncthreads();
    gather_tile(tb + (size_t)g0*plane, sxy, td[0], tid, Hh, Ww);
    __syncthreads();
    for (int gi=0; gi<G_PER; gi++) {
        int g = g0 + gi;
        if (gi+1 < G_PER)
            gather_tile(tb + (size_t)(g+1)*plane, sxy, td[(gi+1)&1], tid, Hh, Ww);
        const float4* tdc = td[gi&1];
        float4 acc0=make_float4(0,0,0,0), acc1=make_float4(0,0,0,0);
        #pragma unroll
        for (int ky=0; ky<4; ky++){
            const float4* trow = &tdc[(2*ty+ky)*34 + tx];
            float4 v0=trow[0], v1=trow[1], v2=trow[2];
            if (ky < 3) {
                const float4* wr = &sdw4[gi*9 + ky*3];
                float4 w0=wr[0], w1=wr[1], w2=wr[2];
                acc0.x += v0.x*w0.x + v1.x*w1.x + v2.x*w2.x;
                acc0.y += v0.y*w0.y + v1.y*w1.y + v2.y*w2.y;
                acc0.z += v0.z*w0.z + v1.z*w1.z + v2.z*w2.z;
                acc0.w += v0.w*w0.w + v1.w*w1.w + v2.w*w2.w;
            }
            if (ky >= 1) {
                const float4* wr = &sdw4[gi*9 + (ky-1)*3];
                float4 w0=wr[0], w1=wr[1], w2=wr[2];
                acc1.x += v0.x*w0.x + v1.x*w1.x + v2.x*w2.x;
                acc1.y += v0.y*w0.y + v1.y*w1.y + v2.y*w2.y;
                acc1.z += v0.z*w0.z + v1.z*w1.z + v2.z*w2.z;
                acc1.w += v0.w*w0.w + v1.w*w1.w + v2.w*w2.w;
            }
        }
        float4 p0=spw[gi*4],p1=spw[gi*4+1],p2=spw[gi*4+2],p3=spw[gi*4+3],wsv=sws[gi];
        float4* og = outp + ((size_t)b*64+g)*plane;
        #pragma unroll
        for (int r=0;r<2;r++){
            float4 ac = r ? acc1 : acc0;
            float r0=fmaxf(ac.x,0.f), r1=fmaxf(ac.y,0.f);
            float r2=fmaxf(ac.z,0.f), r3=fmaxf(ac.w,0.f);
            float4 o;
            o.x=(r0*p0.x+r1*p0.y+r2*p0.z+r3*p0.w)*wsv.x;
            o.y=(r0*p1.x+r1*p1.y+r2*p1.z+r3*p1.w)*wsv.y;
            o.z=(r0*p2.x+r1*p2.y+r2*p2.z+r3*p2.w)*wsv.z;
            o.w=(r0*p3.x+r1*p3.y+r2*p3.z+r3*p3.w)*wsv.w;
            og[(size_t)(py0+r)*Ww + px] = o;
        }
        __syncthreads();
    }
}

// final: level1 iwt (on the fly) + level0 iwt + base depthwise conv + bias*scale + gamma
__global__ void k_final(const float* __restrict__ x, const float4* __restrict__ coef,
                        const float4* __restrict__ tpw1, const float* __restrict__ bw,
                        const float* __restrict__ bb_, const float* __restrict__ bscale,
                        const float* __restrict__ gammap, float* __restrict__ outp) {
    int idx = blockIdx.x*blockDim.x + threadIdx.x;
    int total = BB*CCH*128*128;
    if (idx >= total) return;
    int j = idx % 128; int t = idx / 128;
    int i = t % 128; t /= 128;
    int c = t % CCH; int b = t / CCH;
    size_t ci = ((size_t)(b*CCH+c)*128 + i)*128 + j;
    float4 n = tpw1[((size_t)(b*CCH+c)*64 + (i>>1))*64 + (j>>1)];
    float sA = (i&1)? -1.f : 1.f;
    float sB = (j&1)? -1.f : 1.f;
    float nxtv = 0.5f*(n.x + sA*n.y + sB*n.z + sA*sB*n.w);
    float4 v = coef[ci];
    float LL = v.x + nxtv;
    float A=v.y, Bv=v.z, Cv=v.w;
    float rec[2][2];
    rec[0][0]=0.5f*(LL+A+Bv+Cv); rec[0][1]=0.5f*(LL+A-Bv-Cv);
    rec[1][0]=0.5f*(LL-A+Bv-Cv); rec[1][1]=0.5f*(LL-A-Bv+Cv);
    float gm = gammap[0];
    const float* xp = x + (size_t)(b*CCH+c)*256*256;
    float wreg[9];
    #pragma unroll
    for (int k=0;k<9;k++) wreg[k]=__ldg(&bw[c*9+k]);
    float bias=__ldg(&bb_[c]), sc=__ldg(&bscale[c]);
    float xv[4][4];
    #pragma unroll
    for (int dy=0;dy<4;dy++){
        int yy = 2*i-1+dy;
        #pragma unroll
        for (int dx=0;dx<4;dx++){
            int xx = 2*j-1+dx;
            xv[dy][dx] = (yy>=0&&yy<256&&xx>=0&&xx<256) ? xp[(size_t)yy*256+xx] : 0.f;
        }
    }
    float* op = outp + (size_t)(b*CCH+c)*256*256;
    #pragma unroll
    for (int ri=0;ri<2;ri++)
        #pragma unroll
        for (int rj=0;rj<2;rj++){
            float a = 0.f;
            #pragma unroll
            for (int ky=0;ky<3;ky++)
                #pragma unroll
                for (int kx=0;kx<3;kx++)
                    a += xv[ri+ky][rj+kx]*wreg[ky*3+kx];
            op[(size_t)(2*i+ri)*256 + 2*j+rj] = (a+bias)*sc + gm*rec[ri][rj];
        }
}

extern "C" void kernel_launch(void* const* d_in, const int* in_sizes, int n_in,
                              void* d_out, int out_size) {
    const float* x       = (const float*)d_in[0];
    const float* base_w  = (const float*)d_in[1];
    const float* base_b  = (const float*)d_in[2];
    const float* base_sc = (const float*)d_in[3];
    const float* off_w   = (const float*)d_in[4];
    const float* off_b   = (const float*)d_in[5];
    const float* dw_w    = (const float*)d_in[6];
    const float* pw_w    = (const float*)d_in[7];
    const float* wscale  = (const float*)d_in[8];
    const float* gamma   = (const float*)d_in[9];
    float* out = (float*)d_out;

    float4 *t0, *tpw0, *t1, *tpw1;
    float *ll1, *off0, *off1, *offacc;
    cudaGetSymbolAddress((void**)&t0,   g_t0);
    cudaGetSymbolAddress((void**)&tpw0, g_tpw0);
    cudaGetSymbolAddress((void**)&t1,   g_t1);
    cudaGetSymbolAddress((void**)&tpw1, g_tpw1);
    cudaGetSymbolAddress((void**)&ll1,  g_ll1);
    cudaGetSymbolAddress((void**)&off0, g_off0);
    cudaGetSymbolAddress((void**)&off1, g_off1);
    cudaGetSymbolAddress((void**)&offacc, g_offacc);

    // level 0
    k_wt<<<16384, 256>>>(x, t0, ll1, 256, 256, (size_t)256*256, (size_t)64*256*256);
    k_off2<<<dim3(4,4,32), dim3(32,8)>>>(t0, off_w, offacc, 128, 128);
    k_offfin<<<256, 256>>>(offacc, off_b, (float2*)off0, 128, 128);
    k_sdp<<<dim3(4,8,64), dim3(32,8)>>>(t0, (const float2*)off0, dw_w, pw_w, wscale,
                                        tpw0, 128, 128);
    // level 1
    k_wt<<<4096, 256>>>(ll1, t1, nullptr, 128, 128, (size_t)128*128, (size_t)64*128*128);
    k_off2<<<dim3(2,2,32), dim3(32,8)>>>(t1, off_w + 2*256*9, offacc, 64, 64);
    k_offfin<<<64, 256>>>(offacc, off_b + 2, (float2*)off1, 64, 64);
    k_sdp<<<dim3(2,4,64), dim3(32,8)>>>(t1, (const float2*)off1, dw_w + 256*9,
                                        pw_w + 256*4, wscale + 256, tpw1, 64, 64);
    // reconstruction + base, fused
    k_final<<<16384, 256>>>(x, tpw0, tpw1, base_w, base_b, base_sc, gamma, out);
}

// round 9
// speedup vs baseline: 1.7304x; 1.0475x over previous
#include <cuda_runtime.h>
#include <cuda_pipeline_primitives.h>
#include <math.h>

#define BB 4
#define CCH 64
#define G_PER 4
#define NHALO 612           // 34 x 18 halo points
#define NRAW  836           // 38 x 22 raw t tile

__device__ __align__(16) float g_t0  [(size_t)4*64*128*128*4];
__device__ __align__(16) float g_tpw0[(size_t)4*64*128*128*4];
__device__ __align__(16) float g_t1  [(size_t)4*64*64*64*4];
__device__ __align__(16) float g_tpw1[(size_t)4*64*64*64*4];
__device__ __align__(8) float g_off0[(size_t)4*2*128*128];
__device__ __align__(8) float g_off1[(size_t)4*2*64*64];
__device__ float g_offacc[(size_t)8*4*2*128*128];

// Two-level Haar analysis fused: x(256^2) -> t0(128^2, interleaved) + t1(64^2, interleaved)
__global__ void k_wt2(const float* __restrict__ src, float4* __restrict__ t0,
                      float4* __restrict__ t1) {
    int idx = blockIdx.x * blockDim.x + threadIdx.x;
    int total = BB * CCH * 64 * 64;
    if (idx >= total) return;
    int q = idx & 63; int t = idx >> 6;
    int p = t & 63;  t >>= 6;
    int c = t & 63;  int b = t >> 6;
    const float* s = src + ((size_t)(b*CCH+c)*256 + 4*p)*256 + 4*q;
    float xv[4][4];
    #pragma unroll
    for (int r=0;r<4;r++){
        float2 u = *(const float2*)(s + (size_t)r*256);
        float2 v = *(const float2*)(s + (size_t)r*256 + 2);
        xv[r][0]=u.x; xv[r][1]=u.y; xv[r][2]=v.x; xv[r][3]=v.y;
    }
    float LLs[2][2];
    #pragma unroll
    for (int di=0;di<2;di++)
        #pragma unroll
        for (int dj=0;dj<2;dj++){
            float x00=xv[2*di][2*dj],   x01=xv[2*di][2*dj+1];
            float x10=xv[2*di+1][2*dj], x11=xv[2*di+1][2*dj+1];
            float LL=0.5f*(x00+x01+x10+x11), A=0.5f*(x00+x01-x10-x11);
            float Bv=0.5f*(x00-x01+x10-x11), Cv=0.5f*(x00-x01-x10+x11);
            t0[((size_t)(b*CCH+c)*128 + 2*p+di)*128 + 2*q+dj] = make_float4(LL,A,Bv,Cv);
            LLs[di][dj]=LL;
        }
    float LL2=0.5f*(LLs[0][0]+LLs[0][1]+LLs[1][0]+LLs[1][1]);
    float A2 =0.5f*(LLs[0][0]+LLs[0][1]-LLs[1][0]-LLs[1][1]);
    float B2 =0.5f*(LLs[0][0]-LLs[0][1]+LLs[1][0]-LLs[1][1]);
    float C2 =0.5f*(LLs[0][0]-LLs[0][1]-LLs[1][0]+LLs[1][1]);
    t1[((size_t)(b*CCH+c)*64 + p)*64 + q] = make_float4(LL2,A2,B2,C2);
}

// dense 3x3 conv 256->2, 8-way channel-split partials. grid(W/32,H/32,B*8) block(32,8)
__global__ void k_off2(const float4* __restrict__ t4, const float* __restrict__ ow,
                       float* __restrict__ acc, int Hh, int Ww) {
    __shared__ float wsm[576];
    __shared__ float tile[8][34][34];
    int tx=threadIdx.x, ty=threadIdx.y, tid=ty*32+tx;
    int split = blockIdx.z & 7, b = blockIdx.z >> 3;
    int cb = split*32, gb = split*8;
    for (int i=tid;i<576;i+=256){int o=i/288,rem=i%288;wsm[i]=ow[(o*256+cb+rem/9)*9+rem%9];}
    size_t plane = (size_t)Hh*Ww;
    const float4* tb = t4 + (size_t)b*64*plane;
    int gx0 = blockIdx.x*32-1, gy0 = blockIdx.y*32-1;
    float a0[4]={0,0,0,0}, a1[4]={0,0,0,0};
    for (int gg=0; gg<8; gg+=2) {
        __syncthreads();
        for (int i=tid;i<2*1156;i+=256){
            int g2=i/1156,pos=i%1156,yy=pos/34,xx=pos%34;
            int gy=gy0+yy, gx=gx0+xx;
            float4 v = make_float4(0.f,0.f,0.f,0.f);
            if (gy>=0&&gy<Hh&&gx>=0&&gx<Ww) v = tb[(size_t)(gb+gg+g2)*plane+(size_t)gy*Ww+gx];
            tile[g2*4+0][yy][xx]=v.x; tile[g2*4+1][yy][xx]=v.y;
            tile[g2*4+2][yy][xx]=v.z; tile[g2*4+3][yy][xx]=v.w;
        }
        __syncthreads();
        #pragma unroll
        for (int c8=0;c8<8;c8++){
            int lc = gg*4 + c8;
            float w0[9], w1[9];
            #pragma unroll
            for (int k=0;k<9;k++){w0[k]=wsm[lc*9+k];w1[k]=wsm[288+lc*9+k];}
            float vals[6][3];
            #pragma unroll
            for (int rr=0;rr<6;rr++)
                #pragma unroll
                for (int kx=0;kx<3;kx++) vals[rr][kx]=tile[c8][4*ty+rr][tx+kx];
            #pragma unroll
            for (int r=0;r<4;r++)
                #pragma unroll
                for (int ky=0;ky<3;ky++)
                    #pragma unroll
                    for (int kx=0;kx<3;kx++){
                        float v=vals[r+ky][kx];
                        a0[r]+=v*w0[ky*3+kx]; a1[r]+=v*w1[ky*3+kx];
                    }
        }
    }
    float* ob = acc + (((size_t)split*4 + b)*2)*plane;
    int px = blockIdx.x*32+tx;
    #pragma unroll
    for (int r=0;r<4;r++){
        int py = blockIdx.y*32 + ty*4 + r;
        ob[(size_t)py*Ww+px]=a0[r];
        ob[plane+(size_t)py*Ww+px]=a1[r];
    }
}

__device__ __forceinline__ float reflect_clip(float v, float size) {
    float two = 2.f*size;
    float r = fmodf(v+0.5f, two);
    if (r < 0.f) r += two;
    if (r > size) r = two - r;
    r -= 0.5f;
    return fminf(fmaxf(r, 0.f), size-1.f);
}

// sum 8 partials + bias -> tanh -> reflect-clipped coords, packed float2
__global__ void k_offfin(const float* __restrict__ acc, const float* __restrict__ ob,
                         float2* __restrict__ offmap, int Hh, int Ww) {
    int idx = blockIdx.x*blockDim.x + threadIdx.x;
    int n = BB*Hh*Ww;
    if (idx >= n) return;
    int px = idx % Ww; int t = idx / Ww;
    int py = t % Hh; int b = t / Hh;
    size_t plane = (size_t)Hh*Ww, pix = (size_t)py*Ww+px;
    float s0=0.f, s1=0.f;
    #pragma unroll
    for (int s=0;s<8;s++){
        const float* base = acc + (((size_t)s*4+b)*2)*plane + pix;
        s0 += base[0]; s1 += base[plane];
    }
    float offx = tanhf(s0 + ob[0]);
    float offy = tanhf(s1 + ob[1]);
    float w = (float)Ww, h = (float)Hh;
    float ix = ((float)px + offx) * (w/(w-1.f)) - 0.5f;
    float iy = ((float)py + offy) * (h/(h-1.f)) - 0.5f;
    offmap[(size_t)b*plane + pix] = make_float2(reflect_clip(ix, w), reflect_clip(iy, h));
}

// fused grid_sample + depthwise3x3 + relu + grouped1x1 + wscale, v3:
// |offset|<=1 bounds all bilinear corners into a 38x22 tile -> cp.async tile into smem,
// bilinear gathers become LDS. grid(W/32,H/16,B*16) block(32,8), 2 rows/thread.
__global__ void __launch_bounds__(256, 4)
k_sdp(const float4* __restrict__ t4, const float2* __restrict__ offmap,
      const float* __restrict__ dww, const float* __restrict__ pww,
      const float* __restrict__ wsc, float4* __restrict__ outp,
      int Hh, int Ww) {
    __shared__ __align__(16) int4   sidx[NHALO];
    __shared__ __align__(16) float4 swt [NHALO];
    __shared__ __align__(16) float4 sraw[NRAW];
    __shared__ __align__(16) float4 td  [NHALO];
    __shared__ float4 sdw4[G_PER*9];
    __shared__ float4 spw[G_PER*4];
    __shared__ float4 sws[G_PER];
    int tx=threadIdx.x, ty=threadIdx.y, tid=ty*32+tx;
    int b = blockIdx.z >> 4, g0 = (blockIdx.z & 15)*G_PER;
    if (tid < G_PER*9) {
        int gi = tid/9, k = tid%9, c4 = (g0+gi)*4;
        sdw4[tid] = make_float4(dww[(c4+0)*9+k], dww[(c4+1)*9+k],
                                dww[(c4+2)*9+k], dww[(c4+3)*9+k]);
    }
    if (tid < G_PER*4) spw[tid] = *(const float4*)&pww[(g0*4+tid)*4];
    if (tid < G_PER)   sws[tid] = *(const float4*)&wsc[(g0+tid)*4];
    size_t plane = (size_t)Hh*Ww;
    const float2* ofp = offmap + (size_t)b*plane;
    int gx0 = blockIdx.x*32-1, gy0 = blockIdx.y*16-1;
    int tx0 = gx0-2, ty0 = gy0-2;
    const float4* tb = t4 + (size_t)b*64*plane;
    // prefetch raw tile for first group
    {
        const float4* tg = tb + (size_t)g0*plane;
        for (int i=tid;i<NRAW;i+=256){
            int r=i/38, c=i%38;
            int gy=min(max(ty0+r,0),Hh-1), gx=min(max(tx0+c,0),Ww-1);
            __pipeline_memcpy_async(&sraw[i], &tg[(size_t)gy*Ww+gx], 16);
        }
        __pipeline_commit();
    }
    // precompute bilinear indices (into raw tile) + weights per halo point
    for (int i=tid;i<NHALO;i+=256){
        int xx=i%34, yy=i/34;
        int gx=gx0+xx, gy=gy0+yy;
        int4 ii = make_int4(0,0,0,0);
        float4 wv = make_float4(0.f,0.f,0.f,0.f);
        if (gx>=0&&gx<Ww&&gy>=0&&gy<Hh){
            float2 c = ofp[(size_t)gy*Ww+gx];
            float x0=floorf(c.x), y0=floorf(c.y);
            float wx=c.x-x0, wy=c.y-y0;
            int x0i=(int)x0, y0i=(int)y0;
            int x1i=min(x0i+1,Ww-1), y1i=min(y0i+1,Hh-1);
            int r0=(y0i-ty0)*38, r1=(y1i-ty0)*38;
            int c0=x0i-tx0, c1=x1i-tx0;
            ii = make_int4(r0+c0, r0+c1, r1+c0, r1+c1);
            wv = make_float4((1.f-wy)*(1.f-wx),(1.f-wy)*wx,wy*(1.f-wx),wy*wx);
        }
        sidx[i]=ii; swt[i]=wv;
    }
    int px = blockIdx.x*32+tx, py0 = blockIdx.y*16 + 2*ty;
    __pipeline_wait_prior(0);
    __syncthreads();
    for (int gi=0; gi<G_PER; gi++) {
        int g = g0 + gi;
        // bilinear from smem raw tile -> td
        for (int i=tid;i<NHALO;i+=256){
            int4 ii = sidx[i]; float4 wv = swt[i];
            float4 v00=sraw[ii.x], v01=sraw[ii.y], v10=sraw[ii.z], v11=sraw[ii.w];
            float4 r;
            r.x=v00.x*wv.x+v01.x*wv.y+v10.x*wv.z+v11.x*wv.w;
            r.y=v00.y*wv.x+v01.y*wv.y+v10.y*wv.z+v11.y*wv.w;
            r.z=v00.z*wv.x+v01.z*wv.y+v10.z*wv.z+v11.z*wv.w;
            r.w=v00.w*wv.x+v01.w*wv.y+v10.w*wv.z+v11.w*wv.w;
            td[i]=r;
        }
        __syncthreads();               // td ready; raw tile free to overwrite
        if (gi+1 < G_PER){             // prefetch next group's raw tile
            const float4* tg = tb + (size_t)(g+1)*plane;
            for (int i=tid;i<NRAW;i+=256){
                int r=i/38, c=i%38;
                int gy=min(max(ty0+r,0),Hh-1), gx=min(max(tx0+c,0),Ww-1);
                __pipeline_memcpy_async(&sraw[i], &tg[(size_t)gy*Ww+gx], 16);
            }
            __pipeline_commit();
        }
        float4 acc0=make_float4(0,0,0,0), acc1=make_float4(0,0,0,0);
        #pragma unroll
        for (int ky=0; ky<4; ky++){
            const float4* trow = &td[(2*ty+ky)*34 + tx];
            float4 v0=trow[0], v1=trow[1], v2=trow[2];
            if (ky < 3) {
                const float4* wr = &sdw4[gi*9 + ky*3];
                float4 w0=wr[0], w1=wr[1], w2=wr[2];
                acc0.x += v0.x*w0.x + v1.x*w1.x + v2.x*w2.x;
                acc0.y += v0.y*w0.y + v1.y*w1.y + v2.y*w2.y;
                acc0.z += v0.z*w0.z + v1.z*w1.z + v2.z*w2.z;
                acc0.w += v0.w*w0.w + v1.w*w1.w + v2.w*w2.w;
            }
            if (ky >= 1) {
                const float4* wr = &sdw4[gi*9 + (ky-1)*3];
                float4 w0=wr[0], w1=wr[1], w2=wr[2];
                acc1.x += v0.x*w0.x + v1.x*w1.x + v2.x*w2.x;
                acc1.y += v0.y*w0.y + v1.y*w1.y + v2.y*w2.y;
                acc1.z += v0.z*w0.z + v1.z*w1.z + v2.z*w2.z;
                acc1.w += v0.w*w0.w + v1.w*w1.w + v2.w*w2.w;
            }
        }
        float4 p0=spw[gi*4],p1=spw[gi*4+1],p2=spw[gi*4+2],p3=spw[gi*4+3],wsv=sws[gi];
        float4* og = outp + ((size_t)b*64+g)*plane;
        #pragma unroll
        for (int r=0;r<2;r++){
            float4 ac = r ? acc1 : acc0;
            float r0=fmaxf(ac.x,0.f), r1=fmaxf(ac.y,0.f);
            float r2=fmaxf(ac.z,0.f), r3=fmaxf(ac.w,0.f);
            float4 o;
            o.x=(r0*p0.x+r1*p0.y+r2*p0.z+r3*p0.w)*wsv.x;
            o.y=(r0*p1.x+r1*p1.y+r2*p1.z+r3*p1.w)*wsv.y;
            o.z=(r0*p2.x+r1*p2.y+r2*p2.z+r3*p2.w)*wsv.z;
            o.w=(r0*p3.x+r1*p3.y+r2*p3.z+r3*p3.w)*wsv.w;
            og[(size_t)(py0+r)*Ww + px] = o;
        }
        __pipeline_wait_prior(0);
        __syncthreads();
    }
}

// final: level1 iwt (on the fly) + level0 iwt + base depthwise conv + bias*scale + gamma
__global__ void k_final(const float* __restrict__ x, const float4* __restrict__ coef,
                        const float4* __restrict__ tpw1, const float* __restrict__ bw,
                        const float* __restrict__ bb_, const float* __restrict__ bscale,
                        const float* __restrict__ gammap, float* __restrict__ outp) {
    int idx = blockIdx.x*blockDim.x + threadIdx.x;
    int total = BB*CCH*128*128;
    if (idx >= total) return;
    int j = idx % 128; int t = idx / 128;
    int i = t % 128; t /= 128;
    int c = t % CCH; int b = t / CCH;
    size_t ci = ((size_t)(b*CCH+c)*128 + i)*128 + j;
    float4 n = tpw1[((size_t)(b*CCH+c)*64 + (i>>1))*64 + (j>>1)];
    float sA = (i&1)? -1.f : 1.f;
    float sB = (j&1)? -1.f : 1.f;
    float nxtv = 0.5f*(n.x + sA*n.y + sB*n.z + sA*sB*n.w);
    float4 v = coef[ci];
    float LL = v.x + nxtv;
    float A=v.y, Bv=v.z, Cv=v.w;
    float rec[2][2];
    rec[0][0]=0.5f*(LL+A+Bv+Cv); rec[0][1]=0.5f*(LL+A-Bv-Cv);
    rec[1][0]=0.5f*(LL-A+Bv-Cv); rec[1][1]=0.5f*(LL-A-Bv+Cv);
    float gm = gammap[0];
    const float* xp = x + (size_t)(b*CCH+c)*256*256;
    float wreg[9];
    #pragma unroll
    for (int k=0;k<9;k++) wreg[k]=__ldg(&bw[c*9+k]);
    float bias=__ldg(&bb_[c]), sc=__ldg(&bscale[c]);
    float xv[4][4];
    #pragma unroll
    for (int dy=0;dy<4;dy++){
        int yy = 2*i-1+dy;
        #pragma unroll
        for (int dx=0;dx<4;dx++){
            int xx = 2*j-1+dx;
            xv[dy][dx] = (yy>=0&&yy<256&&xx>=0&&xx<256) ? xp[(size_t)yy*256+xx] : 0.f;
        }
    }
    float* op = outp + (size_t)(b*CCH+c)*256*256;
    #pragma unroll
    for (int ri=0;ri<2;ri++){
        float a2[2];
        #pragma unroll
        for (int rj=0;rj<2;rj++){
            float a = 0.f;
            #pragma unroll
            for (int ky=0;ky<3;ky++)
                #pragma unroll
                for (int kx=0;kx<3;kx++)
                    a += xv[ri+ky][rj+kx]*wreg[ky*3+kx];
            a2[rj] = (a+bias)*sc + gm*rec[ri][rj];
        }
        *(float2*)&op[(size_t)(2*i+ri)*256 + 2*j] = make_float2(a2[0], a2[1]);
    }
}

extern "C" void kernel_launch(void* const* d_in, const int* in_sizes, int n_in,
                              void* d_out, int out_size) {
    const float* x       = (const float*)d_in[0];
    const float* base_w  = (const float*)d_in[1];
    const float* base_b  = (const float*)d_in[2];
    const float* base_sc = (const float*)d_in[3];
    const float* off_w   = (const float*)d_in[4];
    const float* off_b   = (const float*)d_in[5];
    const float* dw_w    = (const float*)d_in[6];
    const float* pw_w    = (const float*)d_in[7];
    const float* wscale  = (const float*)d_in[8];
    const float* gamma   = (const float*)d_in[9];
    float* out = (float*)d_out;

    float4 *t0, *tpw0, *t1, *tpw1;
    float *off0, *off1, *offacc;
    cudaGetSymbolAddress((void**)&t0,   g_t0);
    cudaGetSymbolAddress((void**)&tpw0, g_tpw0);
    cudaGetSymbolAddress((void**)&t1,   g_t1);
    cudaGetSymbolAddress((void**)&tpw1, g_tpw1);
    cudaGetSymbolAddress((void**)&off0, g_off0);
    cudaGetSymbolAddress((void**)&off1, g_off1);
    cudaGetSymbolAddress((void**)&offacc, g_offacc);

    // both wavelet levels in one pass
    k_wt2<<<4096, 256>>>(x, t0, t1);
    // level 0
    k_off2<<<dim3(4,4,32), dim3(32,8)>>>(t0, off_w, offacc, 128, 128);
    k_offfin<<<256, 256>>>(offacc, off_b, (float2*)off0, 128, 128);
    k_sdp<<<dim3(4,8,64), dim3(32,8)>>>(t0, (const float2*)off0, dw_w, pw_w, wscale,
                                        tpw0, 128, 128);
    // level 1
    k_off2<<<dim3(2,2,32), dim3(32,8)>>>(t1, off_w + 2*256*9, offacc, 64, 64);
    k_offfin<<<64, 256>>>(offacc, off_b + 2, (float2*)off1, 64, 64);
    k_sdp<<<dim3(2,4,64), dim3(32,8)>>>(t1, (const float2*)off1, dw_w + 256*9,
                                        pw_w + 256*4, wscale + 256, tpw1, 64, 64);
    // reconstruction + base, fused
    k_final<<<16384, 256>>>(x, tpw0, tpw1, base_w, base_b, base_sc, gamma, out);
}

// round 10
// speedup vs baseline: 1.8150x; 1.0489x over previous
#include <cuda_runtime.h>
#include <cuda_pipeline_primitives.h>
#include <math.h>

#define BB 4
#define CCH 64
#define G_PER 4
#define NHALO 612           // 34 x 18 halo points
#define NRAW  836           // 38 x 22 raw t tile
#define NXT   2244          // 34 x 66 x-tile points
#define SXPITCH 68

__device__ __align__(16) float g_t0  [(size_t)4*64*128*128*4];
__device__ __align__(16) float g_t1  [(size_t)4*64*64*64*4];
__device__ __align__(16) float g_tpw1[(size_t)4*64*64*64*4];
__device__ __align__(8) float g_off0[(size_t)4*2*128*128];
__device__ __align__(8) float g_off1[(size_t)4*2*64*64];
__device__ float g_offacc[(size_t)8*4*2*128*128];

// Two-level Haar analysis fused: x(256^2) -> t0(128^2, interleaved) + t1(64^2, interleaved)
__global__ void k_wt2(const float* __restrict__ src, float4* __restrict__ t0,
                      float4* __restrict__ t1) {
    int idx = blockIdx.x * blockDim.x + threadIdx.x;
    int total = BB * CCH * 64 * 64;
    if (idx >= total) return;
    int q = idx & 63; int t = idx >> 6;
    int p = t & 63;  t >>= 6;
    int c = t & 63;  int b = t >> 6;
    const float* s = src + ((size_t)(b*CCH+c)*256 + 4*p)*256 + 4*q;
    float xv[4][4];
    #pragma unroll
    for (int r=0;r<4;r++){
        float4 u = *(const float4*)(s + (size_t)r*256);
        xv[r][0]=u.x; xv[r][1]=u.y; xv[r][2]=u.z; xv[r][3]=u.w;
    }
    float LLs[2][2];
    #pragma unroll
    for (int di=0;di<2;di++)
        #pragma unroll
        for (int dj=0;dj<2;dj++){
            float x00=xv[2*di][2*dj],   x01=xv[2*di][2*dj+1];
            float x10=xv[2*di+1][2*dj], x11=xv[2*di+1][2*dj+1];
            float LL=0.5f*(x00+x01+x10+x11), A=0.5f*(x00+x01-x10-x11);
            float Bv=0.5f*(x00-x01+x10-x11), Cv=0.5f*(x00-x01-x10+x11);
            t0[((size_t)(b*CCH+c)*128 + 2*p+di)*128 + 2*q+dj] = make_float4(LL,A,Bv,Cv);
            LLs[di][dj]=LL;
        }
    float LL2=0.5f*(LLs[0][0]+LLs[0][1]+LLs[1][0]+LLs[1][1]);
    float A2 =0.5f*(LLs[0][0]+LLs[0][1]-LLs[1][0]-LLs[1][1]);
    float B2 =0.5f*(LLs[0][0]-LLs[0][1]+LLs[1][0]-LLs[1][1]);
    float C2 =0.5f*(LLs[0][0]-LLs[0][1]-LLs[1][0]+LLs[1][1]);
    t1[((size_t)(b*CCH+c)*64 + p)*64 + q] = make_float4(LL2,A2,B2,C2);
}

// dense 3x3 conv 256->2, 8-way channel-split partials. grid(W/32,H/32,B*8) block(32,8)
__global__ void k_off2(const float4* __restrict__ t4, const float* __restrict__ ow,
                       float* __restrict__ acc, int Hh, int Ww) {
    __shared__ float wsm[576];
    __shared__ float tile[8][34][34];
    int tx=threadIdx.x, ty=threadIdx.y, tid=ty*32+tx;
    int split = blockIdx.z & 7, b = blockIdx.z >> 3;
    int cb = split*32, gb = split*8;
    for (int i=tid;i<576;i+=256){int o=i/288,rem=i%288;wsm[i]=ow[(o*256+cb+rem/9)*9+rem%9];}
    size_t plane = (size_t)Hh*Ww;
    const float4* tb = t4 + (size_t)b*64*plane;
    int gx0 = blockIdx.x*32-1, gy0 = blockIdx.y*32-1;
    float a0[4]={0,0,0,0}, a1[4]={0,0,0,0};
    for (int gg=0; gg<8; gg+=2) {
        __syncthreads();
        for (int i=tid;i<2*1156;i+=256){
            int g2=i/1156,pos=i%1156,yy=pos/34,xx=pos%34;
            int gy=gy0+yy, gx=gx0+xx;
            float4 v = make_float4(0.f,0.f,0.f,0.f);
            if (gy>=0&&gy<Hh&&gx>=0&&gx<Ww) v = tb[(size_t)(gb+gg+g2)*plane+(size_t)gy*Ww+gx];
            tile[g2*4+0][yy][xx]=v.x; tile[g2*4+1][yy][xx]=v.y;
            tile[g2*4+2][yy][xx]=v.z; tile[g2*4+3][yy][xx]=v.w;
        }
        __syncthreads();
        #pragma unroll
        for (int c8=0;c8<8;c8++){
            int lc = gg*4 + c8;
            float w0[9], w1[9];
            #pragma unroll
            for (int k=0;k<9;k++){w0[k]=wsm[lc*9+k];w1[k]=wsm[288+lc*9+k];}
            float vals[6][3];
            #pragma unroll
            for (int rr=0;rr<6;rr++)
                #pragma unroll
                for (int kx=0;kx<3;kx++) vals[rr][kx]=tile[c8][4*ty+rr][tx+kx];
            #pragma unroll
            for (int r=0;r<4;r++)
                #pragma unroll
                for (int ky=0;ky<3;ky++)
                    #pragma unroll
                    for (int kx=0;kx<3;kx++){
                        float v=vals[r+ky][kx];
                        a0[r]+=v*w0[ky*3+kx]; a1[r]+=v*w1[ky*3+kx];
                    }
        }
    }
    float* ob = acc + (((size_t)split*4 + b)*2)*plane;
    int px = blockIdx.x*32+tx;
    #pragma unroll
    for (int r=0;r<4;r++){
        int py = blockIdx.y*32 + ty*4 + r;
        ob[(size_t)py*Ww+px]=a0[r];
        ob[plane+(size_t)py*Ww+px]=a1[r];
    }
}

__device__ __forceinline__ float reflect_clip(float v, float size) {
    float two = 2.f*size;
    float r = fmodf(v+0.5f, two);
    if (r < 0.f) r += two;
    if (r > size) r = two - r;
    r -= 0.5f;
    return fminf(fmaxf(r, 0.f), size-1.f);
}

// sum 8 partials + bias -> tanh -> reflect-clipped coords, packed float2
__global__ void k_offfin(const float* __restrict__ acc, const float* __restrict__ ob,
                         float2* __restrict__ offmap, int Hh, int Ww) {
    int idx = blockIdx.x*blockDim.x + threadIdx.x;
    int n = BB*Hh*Ww;
    if (idx >= n) return;
    int px = idx % Ww; int t = idx / Ww;
    int py = t % Hh; int b = t / Hh;
    size_t plane = (size_t)Hh*Ww, pix = (size_t)py*Ww+px;
    float s0=0.f, s1=0.f;
    #pragma unroll
    for (int s=0;s<8;s++){
        const float* base = acc + (((size_t)s*4+b)*2)*plane + pix;
        s0 += base[0]; s1 += base[plane];
    }
    float offx = tanhf(s0 + ob[0]);
    float offy = tanhf(s1 + ob[1]);
    float w = (float)Ww, h = (float)Hh;
    float ix = ((float)px + offx) * (w/(w-1.f)) - 0.5f;
    float iy = ((float)py + offy) * (h/(h-1.f)) - 0.5f;
    offmap[(size_t)b*plane + pix] = make_float2(reflect_clip(ix, w), reflect_clip(iy, h));
}

// ---------------- level-1 snake kernel (round-9 proven version) ----------------
__global__ void __launch_bounds__(256, 4)
k_sdp(const float4* __restrict__ t4, const float2* __restrict__ offmap,
      const float* __restrict__ dww, const float* __restrict__ pww,
      const float* __restrict__ wsc, float4* __restrict__ outp,
      int Hh, int Ww) {
    __shared__ __align__(16) int4   sidx[NHALO];
    __shared__ __align__(16) float4 swt [NHALO];
    __shared__ __align__(16) float4 sraw[NRAW];
    __shared__ __align__(16) float4 td  [NHALO];
    __shared__ float4 sdw4[G_PER*9];
    __shared__ float4 spw[G_PER*4];
    __shared__ float4 sws[G_PER];
    int tx=threadIdx.x, ty=threadIdx.y, tid=ty*32+tx;
    int b = blockIdx.z >> 4, g0 = (blockIdx.z & 15)*G_PER;
    if (tid < G_PER*9) {
        int gi = tid/9, k = tid%9, c4 = (g0+gi)*4;
        sdw4[tid] = make_float4(dww[(c4+0)*9+k], dww[(c4+1)*9+k],
                                dww[(c4+2)*9+k], dww[(c4+3)*9+k]);
    }
    if (tid < G_PER*4) spw[tid] = *(const float4*)&pww[(g0*4+tid)*4];
    if (tid < G_PER)   sws[tid] = *(const float4*)&wsc[(g0+tid)*4];
    size_t plane = (size_t)Hh*Ww;
    const float2* ofp = offmap + (size_t)b*plane;
    int gx0 = blockIdx.x*32-1, gy0 = blockIdx.y*16-1;
    int tx0 = gx0-2, ty0 = gy0-2;
    const float4* tb = t4 + (size_t)b*64*plane;
    {
        const float4* tg = tb + (size_t)g0*plane;
        for (int i=tid;i<NRAW;i+=256){
            int r=i/38, c=i%38;
            int gy=min(max(ty0+r,0),Hh-1), gx=min(max(tx0+c,0),Ww-1);
            __pipeline_memcpy_async(&sraw[i], &tg[(size_t)gy*Ww+gx], 16);
        }
        __pipeline_commit();
    }
    for (int i=tid;i<NHALO;i+=256){
        int xx=i%34, yy=i/34;
        int gx=gx0+xx, gy=gy0+yy;
        int4 ii = make_int4(0,0,0,0);
        float4 wv = make_float4(0.f,0.f,0.f,0.f);
        if (gx>=0&&gx<Ww&&gy>=0&&gy<Hh){
            float2 c = ofp[(size_t)gy*Ww+gx];
            float x0=floorf(c.x), y0=floorf(c.y);
            float wx=c.x-x0, wy=c.y-y0;
            int x0i=(int)x0, y0i=(int)y0;
            int x1i=min(x0i+1,Ww-1), y1i=min(y0i+1,Hh-1);
            int r0=(y0i-ty0)*38, r1=(y1i-ty0)*38;
            int c0=x0i-tx0, c1=x1i-tx0;
            ii = make_int4(r0+c0, r0+c1, r1+c0, r1+c1);
            wv = make_float4((1.f-wy)*(1.f-wx),(1.f-wy)*wx,wy*(1.f-wx),wy*wx);
        }
        sidx[i]=ii; swt[i]=wv;
    }
    int px = blockIdx.x*32+tx, py0 = blockIdx.y*16 + 2*ty;
    __pipeline_wait_prior(0);
    __syncthreads();
    for (int gi=0; gi<G_PER; gi++) {
        int g = g0 + gi;
        for (int i=tid;i<NHALO;i+=256){
            int4 ii = sidx[i]; float4 wv = swt[i];
            float4 v00=sraw[ii.x], v01=sraw[ii.y], v10=sraw[ii.z], v11=sraw[ii.w];
            float4 r;
            r.x=v00.x*wv.x+v01.x*wv.y+v10.x*wv.z+v11.x*wv.w;
            r.y=v00.y*wv.x+v01.y*wv.y+v10.y*wv.z+v11.y*wv.w;
            r.z=v00.z*wv.x+v01.z*wv.y+v10.z*wv.z+v11.z*wv.w;
            r.w=v00.w*wv.x+v01.w*wv.y+v10.w*wv.z+v11.w*wv.w;
            td[i]=r;
        }
        __syncthreads();
        if (gi+1 < G_PER){
            const float4* tg = tb + (size_t)(g+1)*plane;
            for (int i=tid;i<NRAW;i+=256){
                int r=i/38, c=i%38;
                int gy=min(max(ty0+r,0),Hh-1), gx=min(max(tx0+c,0),Ww-1);
                __pipeline_memcpy_async(&sraw[i], &tg[(size_t)gy*Ww+gx], 16);
            }
            __pipeline_commit();
        }
        float4 acc0=make_float4(0,0,0,0), acc1=make_float4(0,0,0,0);
        #pragma unroll
        for (int ky=0; ky<4; ky++){
            const float4* trow = &td[(2*ty+ky)*34 + tx];
            float4 v0=trow[0], v1=trow[1], v2=trow[2];
            if (ky < 3) {
                const float4* wr = &sdw4[gi*9 + ky*3];
                float4 w0=wr[0], w1=wr[1], w2=wr[2];
                acc0.x += v0.x*w0.x + v1.x*w1.x + v2.x*w2.x;
                acc0.y += v0.y*w0.y + v1.y*w1.y + v2.y*w2.y;
                acc0.z += v0.z*w0.z + v1.z*w1.z + v2.z*w2.z;
                acc0.w += v0.w*w0.w + v1.w*w1.w + v2.w*w2.w;
            }
            if (ky >= 1) {
                const float4* wr = &sdw4[gi*9 + (ky-1)*3];
                float4 w0=wr[0], w1=wr[1], w2=wr[2];
                acc1.x += v0.x*w0.x + v1.x*w1.x + v2.x*w2.x;
                acc1.y += v0.y*w0.y + v1.y*w1.y + v2.y*w2.y;
                acc1.z += v0.z*w0.z + v1.z*w1.z + v2.z*w2.z;
                acc1.w += v0.w*w0.w + v1.w*w1.w + v2.w*w2.w;
            }
        }
        float4 p0=spw[gi*4],p1=spw[gi*4+1],p2=spw[gi*4+2],p3=spw[gi*4+3],wsv=sws[gi];
        float4* og = outp + ((size_t)b*64+g)*plane;
        #pragma unroll
        for (int r=0;r<2;r++){
            float4 ac = r ? acc1 : acc0;
            float r0=fmaxf(ac.x,0.f), r1=fmaxf(ac.y,0.f);
            float r2=fmaxf(ac.z,0.f), r3=fmaxf(ac.w,0.f);
            float4 o;
            o.x=(r0*p0.x+r1*p0.y+r2*p0.z+r3*p0.w)*wsv.x;
            o.y=(r0*p1.x+r1*p1.y+r2*p1.z+r3*p1.w)*wsv.y;
            o.z=(r0*p2.x+r1*p2.y+r2*p2.z+r3*p2.w)*wsv.z;
            o.w=(r0*p3.x+r1*p3.y+r2*p3.z+r3*p3.w)*wsv.w;
            og[(size_t)(py0+r)*Ww + px] = o;
        }
        __pipeline_wait_prior(0);
        __syncthreads();
    }
}

// ---------------- level-0 snake + final reconstruction fused ----------------
// grid(4,8,B*16) block(32,8). Per group: snake pipeline -> tpw float4 in regs,
// then iwt0 + nxt(from tpw1) + base depthwise conv on x-tile (smem) + gamma -> out.
__global__ void __launch_bounds__(256, 4)
k_sdpfin(const float4* __restrict__ t4, const float2* __restrict__ offmap,
         const float* __restrict__ dww, const float* __restrict__ pww,
         const float* __restrict__ wsc, const float4* __restrict__ tpw1,
         const float* __restrict__ xin, const float* __restrict__ bw,
         const float* __restrict__ bb_, const float* __restrict__ bscale,
         const float* __restrict__ gammap, float* __restrict__ outp) {
    const int Hh=128, Ww=128;
    __shared__ __align__(16) float4 spack[NHALO];
    __shared__ __align__(16) float4 sraw[NRAW];
    __shared__ __align__(16) float4 td  [NHALO];
    __shared__ __align__(16) float sxf[34*SXPITCH];
    __shared__ float4 sdw4[G_PER*9];
    __shared__ float4 spw[G_PER*4];
    __shared__ float4 sws[G_PER];
    __shared__ float  sbw[G_PER*9];
    __shared__ float  sbb[G_PER], ssc[G_PER];
    int tx=threadIdx.x, ty=threadIdx.y, tid=ty*32+tx;
    int bx=blockIdx.x, by=blockIdx.y;
    int b = blockIdx.z >> 4, g0 = (blockIdx.z & 15)*G_PER;
    if (tid < G_PER*9) {
        int gi = tid/9, k = tid%9, c4 = (g0+gi)*4;
        sdw4[tid] = make_float4(dww[(c4+0)*9+k], dww[(c4+1)*9+k],
                                dww[(c4+2)*9+k], dww[(c4+3)*9+k]);
        sbw[tid] = bw[g0*9 + tid];
    }
    if (tid < G_PER*4) spw[tid] = *(const float4*)&pww[(g0*4+tid)*4];
    if (tid < G_PER) {
        sws[tid] = *(const float4*)&wsc[(g0+tid)*4];
        sbb[tid] = bb_[g0+tid];
        ssc[tid] = bscale[g0+tid];
    }
    float gm = __ldg(gammap);
    size_t plane = (size_t)Hh*Ww;
    const float2* ofp = offmap + (size_t)b*plane;
    int gx0 = bx*32-1, gy0 = by*16-1;
    int tx0 = gx0-2, ty0 = gy0-2;
    const float4* tb = t4 + (size_t)b*64*plane;
    // prefetch group0: t-tile (commit 0) and x-tile (commit 1)
    {
        const float4* tg = tb + (size_t)g0*plane;
        for (int i=tid;i<NRAW;i+=256){
            int r=i/38, c=i%38;
            int gy=min(max(ty0+r,0),Hh-1), gx=min(max(tx0+c,0),Ww-1);
            __pipeline_memcpy_async(&sraw[i], &tg[(size_t)gy*Ww+gx], 16);
        }
        __pipeline_commit();
        const float* xg = xin + ((size_t)b*64+g0)*65536;
        for (int i=tid;i<NXT;i+=256){
            int sr=i/66, sc=i%66;
            int gy=32*by-1+sr, gxc=64*bx-1+sc;
            float* dst = &sxf[sr*SXPITCH+sc];
            if (gy>=0&&gy<256&&gxc>=0&&gxc<256)
                __pipeline_memcpy_async(dst, &xg[(size_t)gy*256+gxc], 4);
            else *dst = 0.f;
        }
        __pipeline_commit();
    }
    // packed bilinear state per halo point
    for (int i=tid;i<NHALO;i+=256){
        int xx=i%34, yy=i/34;
        int gx=gx0+xx, gy=gy0+yy;
        float4 pk = make_float4(__int_as_float(-1), 0.f, 0.f, 0.f);
        if (gx>=0&&gx<Ww&&gy>=0&&gy<Hh){
            float2 c = ofp[(size_t)gy*Ww+gx];
            float x0=floorf(c.x), y0=floorf(c.y);
            int x0i=(int)x0, y0i=(int)y0;
            int dx = min(x0i+1,Ww-1)-x0i;
            int dy38 = (min(y0i+1,Hh-1)-y0i)*38;
            int i0 = (y0i-ty0)*38 + (x0i-tx0);
            pk = make_float4(__int_as_float(i0), __int_as_float(dx | (dy38<<8)),
                             c.x-x0, c.y-y0);
        }
        spack[i]=pk;
    }
    int pxc = bx*32+tx, py0 = by*16 + 2*ty;
    __pipeline_wait_prior(0);
    __syncthreads();
    for (int gi=0; gi<G_PER; gi++) {
        int g = g0 + gi;
        // bilinear from sraw -> td
        for (int i=tid;i<NHALO;i+=256){
            float4 pk = spack[i];
            int i0 = __float_as_int(pk.x);
            float4 r = make_float4(0.f,0.f,0.f,0.f);
            if (i0 >= 0) {
                int code = __float_as_int(pk.y);
                int dx = code & 0xff, dyo = code >> 8;
                float wx = pk.z, wy = pk.w;
                float u = 1.f-wx, v = 1.f-wy;
                float w00=v*u, w01=v*wx, w10=wy*u, w11=wy*wx;
                float4 v00=sraw[i0], v01=sraw[i0+dx], v10=sraw[i0+dyo], v11=sraw[i0+dyo+dx];
                r.x=v00.x*w00+v01.x*w01+v10.x*w10+v11.x*w11;
                r.y=v00.y*w00+v01.y*w01+v10.y*w10+v11.y*w11;
                r.z=v00.z*w00+v01.z*w01+v10.z*w10+v11.z*w11;
                r.w=v00.w*w00+v01.w*w01+v10.w*w10+v11.w*w11;
            }
            td[i]=r;
        }
        __syncthreads();               // td ready; sraw free
        if (gi+1 < G_PER){             // prefetch next t-tile
            const float4* tg = tb + (size_t)(g+1)*plane;
            for (int i=tid;i<NRAW;i+=256){
                int r=i/38, c=i%38;
                int gy=min(max(ty0+r,0),Hh-1), gx=min(max(tx0+c,0),Ww-1);
                __pipeline_memcpy_async(&sraw[i], &tg[(size_t)gy*Ww+gx], 16);
            }
            __pipeline_commit();
        }
        // depthwise + relu + pw
        float4 acc0=make_float4(0,0,0,0), acc1=make_float4(0,0,0,0);
        #pragma unroll
        for (int ky=0; ky<4; ky++){
            const float4* trow = &td[(2*ty+ky)*34 + tx];
            float4 v0=trow[0], v1=trow[1], v2=trow[2];
            if (ky < 3) {
                const float4* wr = &sdw4[gi*9 + ky*3];
                float4 w0=wr[0], w1=wr[1], w2=wr[2];
                acc0.x += v0.x*w0.x + v1.x*w1.x + v2.x*w2.x;
                acc0.y += v0.y*w0.y + v1.y*w1.y + v2.y*w2.y;
                acc0.z += v0.z*w0.z + v1.z*w1.z + v2.z*w2.z;
                acc0.w += v0.w*w0.w + v1.w*w1.w + v2.w*w2.w;
            }
            if (ky >= 1) {
                const float4* wr = &sdw4[gi*9 + (ky-1)*3];
                float4 w0=wr[0], w1=wr[1], w2=wr[2];
                acc1.x += v0.x*w0.x + v1.x*w1.x + v2.x*w2.x;
                acc1.y += v0.y*w0.y + v1.y*w1.y + v2.y*w2.y;
                acc1.z += v0.z*w0.z + v1.z*w1.z + v2.z*w2.z;
                acc1.w += v0.w*w0.w + v1.w*w1.w + v2.w*w2.w;
            }
        }
        float4 p0=spw[gi*4],p1=spw[gi*4+1],p2=spw[gi*4+2],p3=spw[gi*4+3],wsv=sws[gi];
        float4 o0, o1;
        {
            float r0=fmaxf(acc0.x,0.f), r1=fmaxf(acc0.y,0.f);
            float r2=fmaxf(acc0.z,0.f), r3=fmaxf(acc0.w,0.f);
            o0.x=(r0*p0.x+r1*p0.y+r2*p0.z+r3*p0.w)*wsv.x;
            o0.y=(r0*p1.x+r1*p1.y+r2*p1.z+r3*p1.w)*wsv.y;
            o0.z=(r0*p2.x+r1*p2.y+r2*p2.z+r3*p2.w)*wsv.z;
            o0.w=(r0*p3.x+r1*p3.y+r2*p3.z+r3*p3.w)*wsv.w;
            r0=fmaxf(acc1.x,0.f); r1=fmaxf(acc1.y,0.f);
            r2=fmaxf(acc1.z,0.f); r3=fmaxf(acc1.w,0.f);
            o1.x=(r0*p0.x+r1*p0.y+r2*p0.z+r3*p0.w)*wsv.x;
            o1.y=(r0*p1.x+r1*p1.y+r2*p1.z+r3*p1.w)*wsv.y;
            o1.z=(r0*p2.x+r1*p2.y+r2*p2.z+r3*p2.w)*wsv.z;
            o1.w=(r0*p3.x+r1*p3.y+r2*p3.z+r3*p3.w)*wsv.w;
        }
        // wait x-tile for this group (older than t-tile just issued)
        if (gi+1 < G_PER) __pipeline_wait_prior(1);
        else              __pipeline_wait_prior(0);
        // level-1 nxt + level-0 iwt coefficients
        float4 n = tpw1[((size_t)(b*64+g)*64 + (py0>>1))*64 + (pxc>>1)];
        float sB = (pxc & 1) ? -1.f : 1.f;
        float nz = sB*n.z, nw = sB*n.w;
        float LL0 = o0.x + 0.5f*(n.x + n.y + nz + nw);
        float LL1 = o1.x + 0.5f*(n.x - n.y + nz - nw);
        float rec[4][2];
        rec[0][0]=0.5f*(LL0+o0.y+o0.z+o0.w); rec[0][1]=0.5f*(LL0+o0.y-o0.z-o0.w);
        rec[1][0]=0.5f*(LL0-o0.y+o0.z-o0.w); rec[1][1]=0.5f*(LL0-o0.y-o0.z+o0.w);
        rec[2][0]=0.5f*(LL1+o1.y+o1.z+o1.w); rec[2][1]=0.5f*(LL1+o1.y-o1.z-o1.w);
        rec[3][0]=0.5f*(LL1-o1.y+o1.z-o1.w); rec[3][1]=0.5f*(LL1-o1.y-o1.z+o1.w);
        // base conv on x-tile + combine + store
        float bw0=sbw[gi*9],bw1=sbw[gi*9+1],bw2=sbw[gi*9+2];
        float bw3=sbw[gi*9+3],bw4=sbw[gi*9+4],bw5=sbw[gi*9+5];
        float bw6=sbw[gi*9+6],bw7=sbw[gi*9+7],bw8=sbw[gi*9+8];
        float bias=sbb[gi], sc=ssc[gi];
        float* og = outp + ((size_t)b*64+g)*65536;
        int scol = 2*tx, srow0 = 4*ty;
        float r0c[4], r1c[4], r2c[4];
        #pragma unroll
        for (int k=0;k<4;k++){ r0c[k]=sxf[srow0*SXPITCH+scol+k];
                               r1c[k]=sxf[(srow0+1)*SXPITCH+scol+k]; }
        #pragma unroll
        for (int oi=0; oi<4; oi++){
            #pragma unroll
            for (int k=0;k<4;k++) r2c[k]=sxf[(srow0+oi+2)*SXPITCH+scol+k];
            float c0 = r0c[0]*bw0+r0c[1]*bw1+r0c[2]*bw2
                     + r1c[0]*bw3+r1c[1]*bw4+r1c[2]*bw5
                     + r2c[0]*bw6+r2c[1]*bw7+r2c[2]*bw8;
            float c1 = r0c[1]*bw0+r0c[2]*bw1+r0c[3]*bw2
                     + r1c[1]*bw3+r1c[2]*bw4+r1c[3]*bw5
                     + r2c[1]*bw6+r2c[2]*bw7+r2c[3]*bw8;
            int orow = 32*by + 4*ty + oi;
            float ov0 = (c0+bias)*sc + gm*rec[oi][0];
            float ov1 = (c1+bias)*sc + gm*rec[oi][1];
            *(float2*)&og[(size_t)orow*256 + 64*bx + 2*tx] = make_float2(ov0, ov1);
            #pragma unroll
            for (int k=0;k<4;k++){ r0c[k]=r1c[k]; r1c[k]=r2c[k]; }
        }
        __syncthreads();               // all threads done with sxf
        if (gi+1 < G_PER){             // prefetch next x-tile
            const float* xg = xin + ((size_t)b*64+g+1)*65536;
            for (int i=tid;i<NXT;i+=256){
                int sr=i/66, sc=i%66;
                int gy=32*by-1+sr, gxc=64*bx-1+sc;
                float* dst = &sxf[sr*SXPITCH+sc];
                if (gy>=0&&gy<256&&gxc>=0&&gxc<256)
                    __pipeline_memcpy_async(dst, &xg[(size_t)gy*256+gxc], 4);
                else *dst = 0.f;
            }
            __pipeline_commit();
            __pipeline_wait_prior(1);  // ensure next t-tile (sraw) landed
        }
        __syncthreads();
    }
}

extern "C" void kernel_launch(void* const* d_in, const int* in_sizes, int n_in,
                              void* d_out, int out_size) {
    const float* x       = (const float*)d_in[0];
    const float* base_w  = (const float*)d_in[1];
    const float* base_b  = (const float*)d_in[2];
    const float* base_sc = (const float*)d_in[3];
    const float* off_w   = (const float*)d_in[4];
    const float* off_b   = (const float*)d_in[5];
    const float* dw_w    = (const float*)d_in[6];
    const float* pw_w    = (const float*)d_in[7];
    const float* wscale  = (const float*)d_in[8];
    const float* gamma   = (const float*)d_in[9];
    float* out = (float*)d_out;

    float4 *t0, *t1, *tpw1;
    float *off0, *off1, *offacc;
    cudaGetSymbolAddress((void**)&t0,   g_t0);
    cudaGetSymbolAddress((void**)&t1,   g_t1);
    cudaGetSymbolAddress((void**)&tpw1, g_tpw1);
    cudaGetSymbolAddress((void**)&off0, g_off0);
    cudaGetSymbolAddress((void**)&off1, g_off1);
    cudaGetSymbolAddress((void**)&offacc, g_offacc);

    // both wavelet levels in one pass
    k_wt2<<<4096, 256>>>(x, t0, t1);
    // level 1 chain first (tpw1 needed by the fused final kernel)
    k_off2<<<dim3(2,2,32), dim3(32,8)>>>(t1, off_w + 2*256*9, offacc, 64, 64);
    k_offfin<<<64, 256>>>(offacc, off_b + 2, (float2*)off1, 64, 64);
    k_sdp<<<dim3(2,4,64), dim3(32,8)>>>(t1, (const float2*)off1, dw_w + 256*9,
                                        pw_w + 256*4, wscale + 256, tpw1, 64, 64);
    // level 0 offsets
    k_off2<<<dim3(4,4,32), dim3(32,8)>>>(t0, off_w, offacc, 128, 128);
    k_offfin<<<256, 256>>>(offacc, off_b, (float2*)off0, 128, 128);
    // level 0 snake + full reconstruction + base, fused
    k_sdpfin<<<dim3(4,8,64), dim3(32,8)>>>(t0, (const float2*)off0, dw_w, pw_w, wscale,
                                           tpw1, x, base_w, base_b, base_sc, gamma, out);
}